// round 3
// baseline (speedup 1.0000x reference)
#include <cuda_runtime.h>
#include <math.h>

#define B_ 8
#define C_ 64
#define H_ 256
#define W_ 256
#define HP 258
#define NPIX (B_*H_*W_)          // 524288
#define MAIN_BLOCKS 2048
#define SMEM_FLOATS (12288 + 2048 + 4160 + 512 + 512)
#define SMEM_BYTES (SMEM_FLOATS * 4)

// ---- device scratch (allocation-free rule: static __device__ globals) ----
__device__ float g_xt[B_*HP*W_*C_];     // padded, channel-last input  ~135 MB
__device__ float g_om[NPIX*9];          // offsets+mask logits, [b][h][w][9]
__device__ float g_part[MAIN_BLOCKS*128]; // per-block BN partials (sum, sumsq)
__device__ float g_ab[128];             // A[o], B[o] affine for BN epilogue

// ---------------------------------------------------------------- zero pad rows
__global__ void k_zero_pad() {
    int i = blockIdx.x*256 + threadIdx.x;      // 262144 total
    int b = i >> 15;
    int r = (i >> 14) & 1;
    int j = i & 16383;                          // w*64 + c
    g_xt[(b*HP + r*257)*(W_*C_) + j] = 0.f;
}

// ------------------------------------------------- NCHW -> padded channel-last
__global__ void k_transpose(const float* __restrict__ x) {
    __shared__ float tile[32][33];
    int wb = blockIdx.x*32, cb = blockIdx.y*32;
    int b = blockIdx.z >> 8, h = blockIdx.z & 255;
    int tx = threadIdx.x, ty = threadIdx.y;
    #pragma unroll
    for (int i = 0; i < 4; i++) {
        int c = cb + ty + 8*i;
        tile[ty+8*i][tx] = x[((b*C_ + c)*H_ + h)*W_ + wb + tx];
    }
    __syncthreads();
    #pragma unroll
    for (int i = 0; i < 4; i++) {
        int w = wb + ty + 8*i;
        g_xt[((b*HP + h + 1)*W_ + w)*C_ + cb + tx] = tile[tx][ty+8*i];
    }
}

// --------------------------------------------------- offset conv (9 ch, 3x1)
__global__ void k_offset(const float* __restrict__ x,
                         const float* __restrict__ w_off,
                         const float* __restrict__ b_off) {
    __shared__ float wo[1728];
    int tid = threadIdx.x;
    for (int i = tid; i < 1728; i += 256) wo[i] = w_off[i];
    __syncthreads();
    int pix0 = blockIdx.x*512 + tid;
    int pix1 = pix0 + 256;
    int b  = pix0 >> 16;
    int h0 = (pix0 >> 8) & 255, w0 = pix0 & 255;
    int h1 = (pix1 >> 8) & 255, w1 = pix1 & 255;
    float a0[9], a1[9];
    #pragma unroll
    for (int o = 0; o < 9; o++) { a0[o] = b_off[o]; a1[o] = a0[o]; }
    const float* xb = x + b*C_*H_*W_;
    for (int c = 0; c < C_; c++) {
        const float* xc = xb + c*H_*W_;
        float v0[3], v1[3];
        #pragma unroll
        for (int dh = 0; dh < 3; dh++) {
            int r0 = h0 - 1 + dh;
            int r1 = h1 - 1 + dh;
            v0[dh] = (r0 >= 0 && r0 < H_) ? xc[r0*W_ + w0] : 0.f;
            v1[dh] = (r1 >= 0 && r1 < H_) ? xc[r1*W_ + w1] : 0.f;
        }
        #pragma unroll
        for (int o = 0; o < 9; o++) {
            const float* wp = &wo[(o*C_ + c)*3];
            a0[o] += v0[0]*wp[0] + v0[1]*wp[1] + v0[2]*wp[2];
            a1[o] += v1[0]*wp[0] + v1[1]*wp[1] + v1[2]*wp[2];
        }
    }
    #pragma unroll
    for (int o = 0; o < 9; o++) {
        g_om[pix0*9 + o] = a0[o];
        g_om[pix1*9 + o] = a1[o];
    }
}

// ------------------------------------------------------------- main DCN kernel
__global__ void __launch_bounds__(256)
k_main(const float* __restrict__ w_dcn,
       const float* __restrict__ b_dcn,
       float* __restrict__ out) {
    extern __shared__ float sm[];
    float2* wpair = (float2*)sm;                 // [kk][c][lane] pairs (o, o+32)
    float4* s_sh  = (float4*)(sm + 12288);       // per-warp sampled vec, [c].p
    float*  out_sh = sm + 12288 + 2048;          // [64][65]
    float*  redS   = out_sh + 4160;              // [8][64]
    float*  redQ   = redS + 512;

    const float* __restrict__ xt = g_xt;
    const float* __restrict__ om = g_om;

    int tid = threadIdx.x;
    int lane = tid & 31, wid = tid >> 5;

    for (int i = tid; i < 6144; i += 256) {
        int kk = i >> 11;
        int c  = (i >> 5) & 63;
        int ln = i & 31;
        wpair[i] = make_float2(w_dcn[(ln*C_ + c)*3 + kk],
                               w_dcn[((ln+32)*C_ + c)*3 + kk]);
    }
    __syncthreads();

    float bd0 = b_dcn[lane], bd1 = b_dcn[lane+32];
    float sA = 0.f, sB = 0.f, qA = 0.f, qB = 0.f;
    float4* s_w = s_sh + wid*64;

    for (int t = 0; t < 4; t++) {
        int tileIdx = blockIdx.x*4 + t;
        int pixbase = tileIdx*64;
        int b   = pixbase >> 16;
        int h   = (pixbase >> 8) & 255;
        int wx0 = pixbase & 255;

        #pragma unroll
        for (int g = 0; g < 2; g++) {
            int pxl = wid*8 + g*4;
            float a0=0.f,a1=0.f,a2=0.f,a3=0.f;
            float c0=0.f,c1=0.f,c2=0.f,c3=0.f;

            #pragma unroll
            for (int kk = 0; kk < 3; kk++) {
                int   t00=0,t01=0,t10=0,t11=0;
                float q00=0.f,q01=0.f,q10=0.f,q11=0.f;
                if (lane < 4) {
                    int wxp = wx0 + pxl + lane;
                    int pix = (b << 16) + (h << 8) + wxp;
                    const float* omp = om + pix*9;
                    float dy = omp[kk];
                    float dx = omp[3+kk];
                    float mv = 1.f/(1.f + __expf(-omp[6+kk]));
                    float y  = (float)(h + kk) + dy;
                    float xf = (float)wxp + dx;
                    float y0 = floorf(y), x0 = floorf(xf);
                    float fy = y - y0, fx = xf - x0;
                    int iy0 = (int)y0, ix0 = (int)x0;
                    int iy1 = iy0 + 1, ix1 = ix0 + 1;
                    bool vy0 = (iy0 >= 0) && (iy0 <= HP-1);
                    bool vy1 = (iy1 >= 0) && (iy1 <= HP-1);
                    bool vx0 = (ix0 >= 0) && (ix0 <= W_-1);
                    bool vx1 = (ix1 >= 0) && (ix1 <= W_-1);
                    float gy0 = 1.f - fy, gx0 = 1.f - fx;
                    q00 = gy0*gx0*mv; if (!(vy0 && vx0)) q00 = 0.f;
                    q01 = gy0*fx*mv;  if (!(vy0 && vx1)) q01 = 0.f;
                    q10 = fy*gx0*mv;  if (!(vy1 && vx0)) q10 = 0.f;
                    q11 = fy*fx*mv;   if (!(vy1 && vx1)) q11 = 0.f;
                    int cy0 = min(max(iy0,0),HP-1), cy1 = min(max(iy1,0),HP-1);
                    int cx0 = min(max(ix0,0),W_-1), cx1 = min(max(ix1,0),W_-1);
                    int rb = b*HP;
                    t00 = ((rb+cy0)*W_+cx0)*C_;
                    t01 = ((rb+cy0)*W_+cx1)*C_;
                    t10 = ((rb+cy1)*W_+cx0)*C_;
                    t11 = ((rb+cy1)*W_+cx1)*C_;
                }
                __syncwarp();
                #pragma unroll
                for (int p = 0; p < 4; p++) {
                    int   o00 = __shfl_sync(0xffffffffu, t00, p);
                    int   o01 = __shfl_sync(0xffffffffu, t01, p);
                    int   o10 = __shfl_sync(0xffffffffu, t10, p);
                    int   o11 = __shfl_sync(0xffffffffu, t11, p);
                    float p00 = __shfl_sync(0xffffffffu, q00, p);
                    float p01 = __shfl_sync(0xffffffffu, q01, p);
                    float p10 = __shfl_sync(0xffffffffu, q10, p);
                    float p11 = __shfl_sync(0xffffffffu, q11, p);
                    float v0 = p00*xt[o00+lane]    + p01*xt[o01+lane]
                             + p10*xt[o10+lane]    + p11*xt[o11+lane];
                    float v1 = p00*xt[o00+32+lane] + p01*xt[o01+32+lane]
                             + p10*xt[o10+32+lane] + p11*xt[o11+32+lane];
                    ((float*)&s_w[lane])[p]    = v0;
                    ((float*)&s_w[lane+32])[p] = v1;
                }
                __syncwarp();
                const float2* wk = wpair + (kk << 11);
                #pragma unroll 8
                for (int c = 0; c < 64; c++) {
                    float4 sv = s_w[c];
                    float2 wp = wk[(c << 5) + lane];
                    a0 += sv.x*wp.x; c0 += sv.x*wp.y;
                    a1 += sv.y*wp.x; c1 += sv.y*wp.y;
                    a2 += sv.z*wp.x; c2 += sv.z*wp.y;
                    a3 += sv.w*wp.x; c3 += sv.w*wp.y;
                }
                __syncwarp();
            }
            // epilogue: bias, stage to smem, local BN accumulation
            float oa, ob;
            oa = a0 + bd0; ob = c0 + bd1;
            out_sh[lane*65 + pxl+0] = oa; out_sh[(lane+32)*65 + pxl+0] = ob;
            sA += oa; qA += oa*oa; sB += ob; qB += ob*ob;
            oa = a1 + bd0; ob = c1 + bd1;
            out_sh[lane*65 + pxl+1] = oa; out_sh[(lane+32)*65 + pxl+1] = ob;
            sA += oa; qA += oa*oa; sB += ob; qB += ob*ob;
            oa = a2 + bd0; ob = c2 + bd1;
            out_sh[lane*65 + pxl+2] = oa; out_sh[(lane+32)*65 + pxl+2] = ob;
            sA += oa; qA += oa*oa; sB += ob; qB += ob*ob;
            oa = a3 + bd0; ob = c3 + bd1;
            out_sh[lane*65 + pxl+3] = oa; out_sh[(lane+32)*65 + pxl+3] = ob;
            sA += oa; qA += oa*oa; sB += ob; qB += ob*ob;
        }
        __syncthreads();
        // coalesced NCHW store of the 64x64 tile
        int obase = (b*C_*H_ + h)*W_ + wx0;
        #pragma unroll
        for (int rep = 0; rep < 16; rep++) {
            int idx = rep*256 + tid;
            int o = idx >> 6, wl = idx & 63;
            out[obase + o*H_*W_ + wl] = out_sh[o*65 + wl];
        }
        __syncthreads();
    }

    // deterministic per-block BN partials
    redS[wid*64 + lane]      = sA;
    redS[wid*64 + lane + 32] = sB;
    redQ[wid*64 + lane]      = qA;
    redQ[wid*64 + lane + 32] = qB;
    __syncthreads();
    if (tid < 128) {
        int o = tid & 63;
        const float* src = (tid < 64) ? redS : redQ;
        float s = 0.f;
        #pragma unroll
        for (int w = 0; w < 8; w++) s += src[w*64 + o];
        g_part[blockIdx.x*128 + tid] = s;
    }
}

// ------------------------------------------------------ BN stats -> affine A,B
__global__ void k_stats(const float* __restrict__ gamma,
                        const float* __restrict__ beta) {
    int o = blockIdx.x;
    int tid = threadIdx.x;
    __shared__ float rs[256], rq[256];
    float s = 0.f, q = 0.f;
    for (int j = tid; j < MAIN_BLOCKS; j += 256) {
        s += g_part[j*128 + o];
        q += g_part[j*128 + 64 + o];
    }
    rs[tid] = s; rq[tid] = q;
    __syncthreads();
    for (int st = 128; st > 0; st >>= 1) {
        if (tid < st) { rs[tid] += rs[tid+st]; rq[tid] += rq[tid+st]; }
        __syncthreads();
    }
    if (tid == 0) {
        float n = (float)NPIX;
        float mean = rs[0]/n;
        float var  = rq[0]/n - mean*mean;
        float inv  = rsqrtf(var + 1e-5f);
        float A = gamma[o]*inv;
        g_ab[o]      = A;
        g_ab[64 + o] = beta[o] - mean*A;
    }
}

// -------------------------------------------------------- normalize + ReLU
__global__ void k_norm(float* __restrict__ out) {
    int i = blockIdx.x*256 + threadIdx.x;     // float4 index
    int o = (i >> 14) & 63;                   // (i*4 / 65536) % 64
    float A = g_ab[o], Bv = g_ab[64 + o];
    float4 v = ((float4*)out)[i];
    v.x = fmaxf(fmaf(v.x, A, Bv), 0.f);
    v.y = fmaxf(fmaf(v.y, A, Bv), 0.f);
    v.z = fmaxf(fmaf(v.z, A, Bv), 0.f);
    v.w = fmaxf(fmaf(v.w, A, Bv), 0.f);
    ((float4*)out)[i] = v;
}

extern "C" void kernel_launch(void* const* d_in, const int* in_sizes, int n_in,
                              void* d_out, int out_size) {
    const float* x     = (const float*)d_in[0];
    const float* w_off = (const float*)d_in[1];
    const float* b_off = (const float*)d_in[2];
    const float* w_dcn = (const float*)d_in[3];
    const float* b_dcn = (const float*)d_in[4];
    const float* gamma = (const float*)d_in[5];
    const float* beta  = (const float*)d_in[6];
    float* out = (float*)d_out;

    cudaFuncSetAttribute(k_main, cudaFuncAttributeMaxDynamicSharedMemorySize, SMEM_BYTES);

    k_zero_pad<<<1024, 256>>>();
    k_transpose<<<dim3(8, 2, B_*H_), dim3(32, 8)>>>(x);
    k_offset<<<1024, 256>>>(x, w_off, b_off);
    k_main<<<MAIN_BLOCKS, 256, SMEM_BYTES>>>(w_dcn, b_dcn, out);
    k_stats<<<64, 256>>>(gamma, beta);
    k_norm<<<NPIX*C_/4/256, 256>>>(out);
}

// round 5
// speedup vs baseline: 1.1204x; 1.1204x over previous
#include <cuda_runtime.h>
#include <math.h>
#include <stdint.h>

#define B_ 8
#define C_ 64
#define H_ 256
#define W_ 256
#define HP 258
#define NPIX (B_*H_*W_)          // 524288
#define MAIN_BLOCKS 2048
// smem: Ash 192*64 floats + Bsh 192*66 floats
#define ASH_FLOATS (192*64)
#define BSH_FLOATS (192*66)
#define SMEM_BYTES ((ASH_FLOATS + BSH_FLOATS) * 4)

// ---- device scratch (allocation-free rule: static __device__ globals) ----
__device__ float g_xt[B_*HP*W_*C_];     // padded, channel-last input  ~135 MB
__device__ float g_om[NPIX*9];          // offsets+mask logits, [b][h][w][9]
__device__ float g_part[MAIN_BLOCKS*128]; // per-block BN partials (sum, sumsq)
__device__ float g_ab[128];             // A[o], B[o] affine for BN epilogue

// ---- f32x2 helpers (ptxas never auto-fuses FFMA2) ----
__device__ __forceinline__ void ffma2(uint64_t& d, uint64_t a, uint64_t b) {
    asm("fma.rn.f32x2 %0, %1, %2, %3;" : "=l"(d) : "l"(a), "l"(b), "l"(d));
}
__device__ __forceinline__ uint64_t pack2(float lo, float hi) {
    uint64_t r;
    asm("mov.b64 %0, {%1, %2};" : "=l"(r) : "f"(lo), "f"(hi));
    return r;
}
__device__ __forceinline__ void unpack2(float& lo, float& hi, uint64_t v) {
    asm("mov.b64 {%0, %1}, %2;" : "=f"(lo), "=f"(hi) : "l"(v));
}

// ---------------------------------------------------------------- zero pad rows
__global__ void k_zero_pad() {
    int i = blockIdx.x*256 + threadIdx.x;      // 262144 total
    int b = i >> 15;
    int r = (i >> 14) & 1;
    int j = i & 16383;                          // w*64 + c
    g_xt[(b*HP + r*257)*(W_*C_) + j] = 0.f;
}

// ------------------------------------------------- NCHW -> padded channel-last
__global__ void k_transpose(const float* __restrict__ x) {
    __shared__ float tile[32][33];
    int wb = blockIdx.x*32, cb = blockIdx.y*32;
    int b = blockIdx.z >> 8, h = blockIdx.z & 255;
    int tx = threadIdx.x, ty = threadIdx.y;
    #pragma unroll
    for (int i = 0; i < 4; i++) {
        int c = cb + ty + 8*i;
        tile[ty+8*i][tx] = x[((b*C_ + c)*H_ + h)*W_ + wb + tx];
    }
    __syncthreads();
    #pragma unroll
    for (int i = 0; i < 4; i++) {
        int w = wb + ty + 8*i;
        g_xt[((b*HP + h + 1)*W_ + w)*C_ + cb + tx] = tile[tx][ty+8*i];
    }
}

// --------------------------------------------------- offset conv (9 ch, 3x1)
__global__ void k_offset(const float* __restrict__ x,
                         const float* __restrict__ w_off,
                         const float* __restrict__ b_off) {
    __shared__ float wo[1728];
    int tid = threadIdx.x;
    for (int i = tid; i < 1728; i += 256) wo[i] = w_off[i];
    __syncthreads();
    int pix0 = blockIdx.x*512 + tid;
    int pix1 = pix0 + 256;
    int b  = pix0 >> 16;
    int h0 = (pix0 >> 8) & 255, w0 = pix0 & 255;
    int h1 = (pix1 >> 8) & 255, w1 = pix1 & 255;
    float a0[9], a1[9];
    #pragma unroll
    for (int o = 0; o < 9; o++) { a0[o] = b_off[o]; a1[o] = a0[o]; }
    const float* xb = x + b*C_*H_*W_;
    for (int c = 0; c < C_; c++) {
        const float* xc = xb + c*H_*W_;
        float v0[3], v1[3];
        #pragma unroll
        for (int dh = 0; dh < 3; dh++) {
            int r0 = h0 - 1 + dh;
            int r1 = h1 - 1 + dh;
            v0[dh] = (r0 >= 0 && r0 < H_) ? xc[r0*W_ + w0] : 0.f;
            v1[dh] = (r1 >= 0 && r1 < H_) ? xc[r1*W_ + w1] : 0.f;
        }
        #pragma unroll
        for (int o = 0; o < 9; o++) {
            const float* wp = &wo[(o*C_ + c)*3];
            a0[o] += v0[0]*wp[0] + v0[1]*wp[1] + v0[2]*wp[2];
            a1[o] += v1[0]*wp[0] + v1[1]*wp[1] + v1[2]*wp[2];
        }
    }
    #pragma unroll
    for (int o = 0; o < 9; o++) {
        g_om[pix0*9 + o] = a0[o];
        g_om[pix1*9 + o] = a1[o];
    }
}

// ------------------------------------------------------------- main DCN kernel
// Per 64-pixel tile: gather -> smem B[192][66], then register-tiled GEMM
//   out[64 o][64 pix] = A[192 k][64 o]^T * B[192 k][64 pix]
// Thread tile: 8 outputs x 4 pixels, K split in two halves over 256 threads.
// f32x2 accumulators hold output pairs {o, o+1}.
__global__ void __launch_bounds__(256, 2)
k_main(const float* __restrict__ w_dcn,
       const float* __restrict__ b_dcn,
       float* __restrict__ out) {
    extern __shared__ float sm[];
    float* Ash = sm;                 // [192][64] permuted cols
    float* Bsh = sm + ASH_FLOATS;    // [192][66]

    const float* __restrict__ xt = g_xt;
    const float* __restrict__ om = g_om;

    int tid = threadIdx.x;
    int lane = tid & 31, wid = tid >> 5;

    // ---- load A with permuted columns: col = j*16 + rg*2 + e  (o = rg*8+2j+e)
    for (int i = tid; i < ASH_FLOATS; i += 256) {
        int k   = i >> 6;
        int col = i & 63;
        int j  = col >> 4;
        int rg = (col >> 1) & 7;
        int e  = col & 1;
        int o  = rg*8 + j*2 + e;
        int c  = k & 63, kk = k >> 6;
        Ash[i] = w_dcn[(o*C_ + c)*3 + kk];
    }

    // ---- GEMM thread coords
    int kp = tid >> 7;          // K-partition: 0 -> k[0,96), 1 -> k[96,192)
    int tl = tid & 127;
    int rg = tl & 7;            // output row-group (8 outputs each)
    int cg = tl >> 3;           // pixel col-group (4 pixels each), 0..15

    float bd[8];
    #pragma unroll
    for (int jj = 0; jj < 8; jj++) bd[jj] = b_dcn[rg*8 + jj];
    float s8[8], q8[8];
    #pragma unroll
    for (int jj = 0; jj < 8; jj++) { s8[jj] = 0.f; q8[jj] = 0.f; }

    __syncthreads();

    for (int t = 0; t < 4; t++) {
        int tileIdx = blockIdx.x*4 + t;
        int pixbase = tileIdx*64;
        int b  = pixbase >> 16;
        int h  = (pixbase >> 8) & 255;
        int w0 = pixbase & 255;

        // ================= gather: 192 taps -> Bsh[kk*64+c][pix] =============
        #pragma unroll
        for (int it = 0; it < 6; it++) {
            int T   = wid*24 + it*4;     // taps T..T+3, same kk (T%64 <= 60)
            int kk  = T >> 6;
            int px0 = T & 63;
            int   t00=0,t01=0,t10=0,t11=0;
            float q00=0.f,q01=0.f,q10=0.f,q11=0.f;
            if (lane < 4) {
                int pixw = px0 + lane;
                int wxp  = w0 + pixw;
                const float* omp = om + (((b << 8) + h)*256 + wxp)*9;
                float dy = omp[kk];
                float dx = omp[3+kk];
                float mv = 1.f/(1.f + __expf(-omp[6+kk]));
                float y  = (float)(h + kk) + dy;
                float xf = (float)wxp + dx;
                float y0 = floorf(y), x0 = floorf(xf);
                float fy = y - y0, fx = xf - x0;
                int iy0 = (int)y0, ix0 = (int)x0;
                int iy1 = iy0 + 1, ix1 = ix0 + 1;
                bool vy0 = (iy0 >= 0) && (iy0 <= HP-1);
                bool vy1 = (iy1 >= 0) && (iy1 <= HP-1);
                bool vx0 = (ix0 >= 0) && (ix0 <= W_-1);
                bool vx1 = (ix1 >= 0) && (ix1 <= W_-1);
                float gy0 = 1.f - fy, gx0 = 1.f - fx;
                q00 = gy0*gx0*mv; if (!(vy0 && vx0)) q00 = 0.f;
                q01 = gy0*fx*mv;  if (!(vy0 && vx1)) q01 = 0.f;
                q10 = fy*gx0*mv;  if (!(vy1 && vx0)) q10 = 0.f;
                q11 = fy*fx*mv;   if (!(vy1 && vx1)) q11 = 0.f;
                int cy0 = min(max(iy0,0),HP-1), cy1 = min(max(iy1,0),HP-1);
                int cx0 = min(max(ix0,0),W_-1), cx1 = min(max(ix1,0),W_-1);
                int rb = b*HP;
                t00 = ((rb+cy0)*W_+cx0)*C_;
                t01 = ((rb+cy0)*W_+cx1)*C_;
                t10 = ((rb+cy1)*W_+cx0)*C_;
                t11 = ((rb+cy1)*W_+cx1)*C_;
            }
            __syncwarp();
            #pragma unroll
            for (int p = 0; p < 4; p++) {
                int   o00 = __shfl_sync(0xffffffffu, t00, p);
                int   o01 = __shfl_sync(0xffffffffu, t01, p);
                int   o10 = __shfl_sync(0xffffffffu, t10, p);
                int   o11 = __shfl_sync(0xffffffffu, t11, p);
                float p00 = __shfl_sync(0xffffffffu, q00, p);
                float p01 = __shfl_sync(0xffffffffu, q01, p);
                float p10 = __shfl_sync(0xffffffffu, q10, p);
                float p11 = __shfl_sync(0xffffffffu, q11, p);
                float v0 = p00*xt[o00+lane]    + p01*xt[o01+lane]
                         + p10*xt[o10+lane]    + p11*xt[o11+lane];
                float v1 = p00*xt[o00+32+lane] + p01*xt[o01+32+lane]
                         + p10*xt[o10+32+lane] + p11*xt[o11+32+lane];
                int col = px0 + p;
                Bsh[(kk*64 + lane)*66 + col]      = v0;
                Bsh[(kk*64 + lane + 32)*66 + col] = v1;
            }
        }
        __syncthreads();

        // ================= GEMM (f32x2), each thread 8 out x 4 pix ===========
        uint64_t acc[16];   // acc[p*4+j] = f32x2 {o=rg*8+2j, o+1} for pixel p
        #pragma unroll
        for (int i = 0; i < 16; i++) acc[i] = 0ull;

        {
            const float* Ap = Ash + (kp*96)*64 + rg*2;
            const float* Bp = Bsh + (kp*96)*66 + cg*4;
            #pragma unroll 2
            for (int k = 0; k < 96; k++) {
                uint64_t a0 = *(const uint64_t*)(Ap);
                uint64_t a1 = *(const uint64_t*)(Ap + 16);
                uint64_t a2 = *(const uint64_t*)(Ap + 32);
                uint64_t a3 = *(const uint64_t*)(Ap + 48);
                uint64_t bA = *(const uint64_t*)(Bp);
                uint64_t bB = *(const uint64_t*)(Bp + 2);
                float b0f, b1f, b2f, b3f;
                unpack2(b0f, b1f, bA);
                unpack2(b2f, b3f, bB);
                uint64_t bb0 = pack2(b0f, b0f);
                uint64_t bb1 = pack2(b1f, b1f);
                uint64_t bb2 = pack2(b2f, b2f);
                uint64_t bb3 = pack2(b3f, b3f);
                ffma2(acc[0],  a0, bb0); ffma2(acc[1],  a1, bb0);
                ffma2(acc[2],  a2, bb0); ffma2(acc[3],  a3, bb0);
                ffma2(acc[4],  a0, bb1); ffma2(acc[5],  a1, bb1);
                ffma2(acc[6],  a2, bb1); ffma2(acc[7],  a3, bb1);
                ffma2(acc[8],  a0, bb2); ffma2(acc[9],  a1, bb2);
                ffma2(acc[10], a2, bb2); ffma2(acc[11], a3, bb2);
                ffma2(acc[12], a0, bb3); ffma2(acc[13], a1, bb3);
                ffma2(acc[14], a2, bb3); ffma2(acc[15], a3, bb3);
                Ap += 64;
                Bp += 66;
            }
        }
        __syncthreads();

        // ================= combine K-partitions + epilogue ===================
        float* ex  = Bsh;            // [64 pix][66]: kp1 partials, [pix][o]
        float* osh = Bsh + 4352;     // [64 o][65]: final values for store

        if (kp == 1) {
            #pragma unroll
            for (int p = 0; p < 4; p++) {
                int pix = cg*4 + p;
                #pragma unroll
                for (int j = 0; j < 4; j++)
                    *(uint64_t*)&ex[pix*66 + rg*8 + 2*j] = acc[p*4 + j];
            }
        }
        __syncthreads();
        if (kp == 0) {
            #pragma unroll
            for (int p = 0; p < 4; p++) {
                int pix = cg*4 + p;
                #pragma unroll
                for (int j = 0; j < 4; j++) {
                    float px, py, vx, vy;
                    unpack2(vx, vy, acc[p*4 + j]);
                    unpack2(px, py, *(const uint64_t*)&ex[pix*66 + rg*8 + 2*j]);
                    vx += px + bd[2*j];
                    vy += py + bd[2*j+1];
                    s8[2*j]   += vx; q8[2*j]   += vx*vx;
                    s8[2*j+1] += vy; q8[2*j+1] += vy*vy;
                    int o = rg*8 + 2*j;
                    osh[o*65 + pix]     = vx;
                    osh[(o+1)*65 + pix] = vy;
                }
            }
        }
        __syncthreads();

        // coalesced NCHW store of the 64x64 tile
        int obase = (b*C_*H_ + h)*W_ + w0;
        #pragma unroll
        for (int rep = 0; rep < 16; rep++) {
            int idx = rep*256 + tid;
            int o = idx >> 6, wl = idx & 63;
            out[obase + o*H_*W_ + wl] = osh[o*65 + wl];
        }
        __syncthreads();
    }

    // ---- deterministic per-block BN partials (kp0 threads hold all sums) ----
    if (kp == 0) {
        #pragma unroll
        for (int jj = 0; jj < 8; jj++) {
            int o = rg*8 + jj;
            Bsh[o*16 + cg]        = s8[jj];
            Bsh[1024 + o*16 + cg] = q8[jj];
        }
    }
    __syncthreads();
    if (tid < 128) {
        int o = tid & 63, sel = tid >> 6;
        const float* src = Bsh + sel*1024 + o*16;
        float s = 0.f;
        #pragma unroll
        for (int w = 0; w < 16; w++) s += src[w];
        g_part[blockIdx.x*128 + sel*64 + o] = s;
    }
}

// ------------------------------------------------------ BN stats -> affine A,B
__global__ void k_stats(const float* __restrict__ gamma,
                        const float* __restrict__ beta) {
    int o = blockIdx.x;
    int tid = threadIdx.x;
    __shared__ float rs[256], rq[256];
    float s = 0.f, q = 0.f;
    for (int j = tid; j < MAIN_BLOCKS; j += 256) {
        s += g_part[j*128 + o];
        q += g_part[j*128 + 64 + o];
    }
    rs[tid] = s; rq[tid] = q;
    __syncthreads();
    for (int st = 128; st > 0; st >>= 1) {
        if (tid < st) { rs[tid] += rs[tid+st]; rq[tid] += rq[tid+st]; }
        __syncthreads();
    }
    if (tid == 0) {
        float n = (float)NPIX;
        float mean = rs[0]/n;
        float var  = rq[0]/n - mean*mean;
        float inv  = rsqrtf(var + 1e-5f);
        float A = gamma[o]*inv;
        g_ab[o]      = A;
        g_ab[64 + o] = beta[o] - mean*A;
    }
}

// -------------------------------------------------------- normalize + ReLU
__global__ void k_norm(float* __restrict__ out) {
    int i = blockIdx.x*256 + threadIdx.x;     // float4 index
    int o = (i >> 14) & 63;                   // (i*4 / 65536) % 64
    float A = g_ab[o], Bv = g_ab[64 + o];
    float4 v = ((float4*)out)[i];
    v.x = fmaxf(fmaf(v.x, A, Bv), 0.f);
    v.y = fmaxf(fmaf(v.y, A, Bv), 0.f);
    v.z = fmaxf(fmaf(v.z, A, Bv), 0.f);
    v.w = fmaxf(fmaf(v.w, A, Bv), 0.f);
    ((float4*)out)[i] = v;
}

extern "C" void kernel_launch(void* const* d_in, const int* in_sizes, int n_in,
                              void* d_out, int out_size) {
    const float* x     = (const float*)d_in[0];
    const float* w_off = (const float*)d_in[1];
    const float* b_off = (const float*)d_in[2];
    const float* w_dcn = (const float*)d_in[3];
    const float* b_dcn = (const float*)d_in[4];
    const float* gamma = (const float*)d_in[5];
    const float* beta  = (const float*)d_in[6];
    float* out = (float*)d_out;

    cudaFuncSetAttribute(k_main, cudaFuncAttributeMaxDynamicSharedMemorySize, SMEM_BYTES);

    k_zero_pad<<<1024, 256>>>();
    k_transpose<<<dim3(8, 2, B_*H_), dim3(32, 8)>>>(x);
    k_offset<<<1024, 256>>>(x, w_off, b_off);
    k_main<<<MAIN_BLOCKS, 256, SMEM_BYTES>>>(w_dcn, b_dcn, out);
    k_stats<<<64, 256>>>(gamma, beta);
    k_norm<<<NPIX*C_/4/256, 256>>>(out);
}

// round 6
// speedup vs baseline: 1.1340x; 1.0122x over previous
#include <cuda_runtime.h>
#include <math.h>
#include <stdint.h>

#define B_ 8
#define C_ 64
#define H_ 256
#define W_ 256
#define HP 258
#define NPIX (B_*H_*W_)          // 524288
#define MAIN_BLOCKS 2048
// smem: Ash 192*64 + Bsh 64*196 + meta 608
#define ASH_FLOATS (192*64)
#define BSH_FLOATS (64*196)
#define META_FLOATS 608
#define SMEM_FLOATS (ASH_FLOATS + BSH_FLOATS + META_FLOATS)
#define SMEM_BYTES (SMEM_FLOATS * 4)

// ---- device scratch (allocation-free rule: static __device__ globals) ----
__device__ float g_xt[B_*HP*W_*C_];     // padded, channel-last input  ~135 MB
__device__ float g_om[NPIX*9];          // offsets+mask logits, [b][h][w][9]
__device__ float g_part[MAIN_BLOCKS*128]; // per-block BN partials (sum, sumsq)
__device__ float g_ab[128];             // A[o], B[o] affine for BN epilogue

// ---- f32x2 helpers (ptxas never auto-fuses FFMA2) ----
__device__ __forceinline__ void ffma2(uint64_t& d, uint64_t a, uint64_t b) {
    asm("fma.rn.f32x2 %0, %1, %2, %3;" : "=l"(d) : "l"(a), "l"(b), "l"(d));
}
__device__ __forceinline__ uint64_t pack2(float lo, float hi) {
    uint64_t r;
    asm("mov.b64 %0, {%1, %2};" : "=l"(r) : "f"(lo), "f"(hi));
    return r;
}
__device__ __forceinline__ void unpack2(float& lo, float& hi, uint64_t v) {
    asm("mov.b64 {%0, %1}, %2;" : "=f"(lo), "=f"(hi) : "l"(v));
}

// ---------------------------------------------------------------- zero pad rows
__global__ void k_zero_pad() {
    int i = blockIdx.x*256 + threadIdx.x;      // 262144 total
    int b = i >> 15;
    int r = (i >> 14) & 1;
    int j = i & 16383;                          // w*64 + c
    g_xt[(b*HP + r*257)*(W_*C_) + j] = 0.f;
}

// ------------------------------------------------- NCHW -> padded channel-last
__global__ void k_transpose(const float* __restrict__ x) {
    __shared__ float tile[32][33];
    int wb = blockIdx.x*32, cb = blockIdx.y*32;
    int b = blockIdx.z >> 8, h = blockIdx.z & 255;
    int tx = threadIdx.x, ty = threadIdx.y;
    #pragma unroll
    for (int i = 0; i < 4; i++) {
        int c = cb + ty + 8*i;
        tile[ty+8*i][tx] = x[((b*C_ + c)*H_ + h)*W_ + wb + tx];
    }
    __syncthreads();
    #pragma unroll
    for (int i = 0; i < 4; i++) {
        int w = wb + ty + 8*i;
        g_xt[((b*HP + h + 1)*W_ + w)*C_ + cb + tx] = tile[tx][ty+8*i];
    }
}

// --------------------------------------------------- offset conv (9 ch, 3x1)
__global__ void k_offset(const float* __restrict__ x,
                         const float* __restrict__ w_off,
                         const float* __restrict__ b_off) {
    __shared__ float wo[1728];
    int tid = threadIdx.x;
    for (int i = tid; i < 1728; i += 256) wo[i] = w_off[i];
    __syncthreads();
    int pix0 = blockIdx.x*512 + tid;
    int pix1 = pix0 + 256;
    int b  = pix0 >> 16;
    int h0 = (pix0 >> 8) & 255, w0 = pix0 & 255;
    int h1 = (pix1 >> 8) & 255, w1 = pix1 & 255;
    float a0[9], a1[9];
    #pragma unroll
    for (int o = 0; o < 9; o++) { a0[o] = b_off[o]; a1[o] = a0[o]; }
    const float* xb = x + b*C_*H_*W_;
    for (int c = 0; c < C_; c++) {
        const float* xc = xb + c*H_*W_;
        float v0[3], v1[3];
        #pragma unroll
        for (int dh = 0; dh < 3; dh++) {
            int r0 = h0 - 1 + dh;
            int r1 = h1 - 1 + dh;
            v0[dh] = (r0 >= 0 && r0 < H_) ? xc[r0*W_ + w0] : 0.f;
            v1[dh] = (r1 >= 0 && r1 < H_) ? xc[r1*W_ + w1] : 0.f;
        }
        #pragma unroll
        for (int o = 0; o < 9; o++) {
            const float* wp = &wo[(o*C_ + c)*3];
            a0[o] += v0[0]*wp[0] + v0[1]*wp[1] + v0[2]*wp[2];
            a1[o] += v1[0]*wp[0] + v1[1]*wp[1] + v1[2]*wp[2];
        }
    }
    #pragma unroll
    for (int o = 0; o < 9; o++) {
        g_om[pix0*9 + o] = a0[o];
        g_om[pix1*9 + o] = a1[o];
    }
}

// ------------------------------------------------------------- main DCN kernel
// Per 64-pixel tile:
//   stage om -> meta smem; gather taps (f32x2) -> Bsh[pix][192] (XOR-swizzled
//   16B chunks); register-tiled f32x2 GEMM out[64 o][64 pix], thread tile
//   8 outputs x 4 pixels, K split in 2 halves.
__global__ void __launch_bounds__(256, 2)
k_main(const float* __restrict__ w_dcn,
       const float* __restrict__ b_dcn,
       float* __restrict__ out) {
    extern __shared__ float sm[];
    float* Ash  = sm;                       // [192][64], col = half*32+rg*4+cc
    float* Bsh  = sm + ASH_FLOATS;          // [64 pix][196], chunk-swizzled
    float* meta = sm + ASH_FLOATS + BSH_FLOATS;  // [9 ch][66 pix]

    const float* __restrict__ xt = g_xt;
    const float* __restrict__ om = g_om;

    int tid = threadIdx.x;
    int lane = tid & 31, wid = tid >> 5;

    // ---- load A: Ash[k][half*32 + rg*4 + cc] = w_dcn[o][c][kk], o=rg*8+half*4+cc
    for (int i = tid; i < ASH_FLOATS; i += 256) {
        int k    = i >> 6;
        int col  = i & 63;
        int half = col >> 5;
        int rg   = (col >> 2) & 7;
        int cc   = col & 3;
        int o    = rg*8 + half*4 + cc;
        int c    = k & 63, kk = k >> 6;
        Ash[i] = w_dcn[(o*C_ + c)*3 + kk];
    }

    // ---- GEMM thread coords
    int kp = tid >> 7;          // K-partition: 0 -> k[0,96), 1 -> k[96,192)
    int tl = tid & 127;
    int rg = tl & 7;            // output row-group (8 outputs each)
    int cg = tl >> 3;           // pixel col-group (4 pixels each), 0..15

    float bd[8];
    #pragma unroll
    for (int jj = 0; jj < 8; jj++) bd[jj] = b_dcn[rg*8 + jj];
    float s8[8], q8[8];
    #pragma unroll
    for (int jj = 0; jj < 8; jj++) { s8[jj] = 0.f; q8[jj] = 0.f; }

    __syncthreads();

    for (int t = 0; t < 4; t++) {
        int tileIdx = blockIdx.x*4 + t;
        int pixbase = tileIdx*64;
        int b  = pixbase >> 16;
        int h  = (pixbase >> 8) & 255;
        int w0 = pixbase & 255;

        // ================= stage om -> meta (sigmoid applied) =================
        for (int i = tid; i < 576; i += 256) {
            int pix = i / 9, ch = i - pix*9;
            float v = om[pixbase*9 + i];
            if (ch >= 6) v = 1.f/(1.f + __expf(-v));
            meta[ch*66 + pix] = v;
        }
        __syncthreads();

        // ================= gather: 192 taps -> Bsh[pix][k] ====================
        #pragma unroll
        for (int it = 0; it < 6; it++) {
            int T   = wid*24 + it*4;     // taps T..T+3, same kk
            int kk  = T >> 6;
            int px0 = T & 63;
            int   t00=0,t01=0,t10=0,t11=0;
            float q00=0.f,q01=0.f,q10=0.f,q11=0.f;
            if (lane < 4) {
                int pixw = px0 + lane;
                int wxp  = w0 + pixw;
                float dy = meta[(0+kk)*66 + pixw];
                float dx = meta[(3+kk)*66 + pixw];
                float mv = meta[(6+kk)*66 + pixw];
                float y  = (float)(h + kk) + dy;
                float xf = (float)wxp + dx;
                float y0 = floorf(y), x0 = floorf(xf);
                float fy = y - y0, fx = xf - x0;
                int iy0 = (int)y0, ix0 = (int)x0;
                int iy1 = iy0 + 1, ix1 = ix0 + 1;
                bool vy0 = (iy0 >= 0) && (iy0 <= HP-1);
                bool vy1 = (iy1 >= 0) && (iy1 <= HP-1);
                bool vx0 = (ix0 >= 0) && (ix0 <= W_-1);
                bool vx1 = (ix1 >= 0) && (ix1 <= W_-1);
                float gy0 = 1.f - fy, gx0 = 1.f - fx;
                q00 = gy0*gx0*mv; if (!(vy0 && vx0)) q00 = 0.f;
                q01 = gy0*fx*mv;  if (!(vy0 && vx1)) q01 = 0.f;
                q10 = fy*gx0*mv;  if (!(vy1 && vx0)) q10 = 0.f;
                q11 = fy*fx*mv;   if (!(vy1 && vx1)) q11 = 0.f;
                int cy0 = min(max(iy0,0),HP-1), cy1 = min(max(iy1,0),HP-1);
                int cx0 = min(max(ix0,0),W_-1), cx1 = min(max(ix1,0),W_-1);
                int rb = b*HP;
                t00 = ((rb+cy0)*W_+cx0)*C_;
                t01 = ((rb+cy0)*W_+cx1)*C_;
                t10 = ((rb+cy1)*W_+cx0)*C_;
                t11 = ((rb+cy1)*W_+cx1)*C_;
            }
            __syncwarp();
            #pragma unroll
            for (int p = 0; p < 4; p++) {
                int   o00 = __shfl_sync(0xffffffffu, t00, p);
                int   o01 = __shfl_sync(0xffffffffu, t01, p);
                int   o10 = __shfl_sync(0xffffffffu, t10, p);
                int   o11 = __shfl_sync(0xffffffffu, t11, p);
                float p00 = __shfl_sync(0xffffffffu, q00, p);
                float p01 = __shfl_sync(0xffffffffu, q01, p);
                float p10 = __shfl_sync(0xffffffffu, q10, p);
                float p11 = __shfl_sync(0xffffffffu, q11, p);
                uint64_t pp00 = pack2(p00, p00);
                uint64_t pp01 = pack2(p01, p01);
                uint64_t pp10 = pack2(p10, p10);
                uint64_t pp11 = pack2(p11, p11);
                // lane handles channels {2*lane, 2*lane+1}
                uint64_t x00 = *((const uint64_t*)(xt + o00) + lane);
                uint64_t x01 = *((const uint64_t*)(xt + o01) + lane);
                uint64_t x10 = *((const uint64_t*)(xt + o10) + lane);
                uint64_t x11 = *((const uint64_t*)(xt + o11) + lane);
                uint64_t v = 0ull;
                ffma2(v, x00, pp00);
                ffma2(v, x01, pp01);
                ffma2(v, x10, pp10);
                ffma2(v, x11, pp11);
                int pixg = px0 + p;
                int key  = (pixg >> 2) & 3;
                int kidx = kk*64 + 2*lane;
                *(uint64_t*)(Bsh + pixg*196 + (((kidx >> 2) ^ key) << 2) + (kidx & 3)) = v;
            }
        }
        __syncthreads();

        // ================= GEMM (f32x2), each thread 8 out x 4 pix ===========
        uint64_t acc[16];   // acc[p*4+q] = pair {o=rg*8+2q, o+1} for pixel p
        #pragma unroll
        for (int i = 0; i < 16; i++) acc[i] = 0ull;

        {
            const float* Ap = Ash + (kp*96)*64 + rg*4;
            const float* B0 = Bsh + (cg*4+0)*196;
            const float* B1 = Bsh + (cg*4+1)*196;
            const float* B2 = Bsh + (cg*4+2)*196;
            const float* B3 = Bsh + (cg*4+3)*196;
            int key = cg & 3;   // (pix>>2)&3, same for all 4 pixels of thread
            #pragma unroll 2
            for (int kb = 0; kb < 96; kb += 4) {
                int ch = ((kp*96 + kb) >> 2) ^ key;
                float4 b0 = *(const float4*)(B0 + (ch << 2));
                float4 b1 = *(const float4*)(B1 + (ch << 2));
                float4 b2 = *(const float4*)(B2 + (ch << 2));
                float4 b3 = *(const float4*)(B3 + (ch << 2));
                #pragma unroll
                for (int j = 0; j < 4; j++) {
                    const float* Ak = Ap + (kb + j)*64;
                    ulonglong2 a01 = *(const ulonglong2*)(Ak);
                    ulonglong2 a23 = *(const ulonglong2*)(Ak + 32);
                    float f0 = ((const float*)&b0)[j];
                    float f1 = ((const float*)&b1)[j];
                    float f2 = ((const float*)&b2)[j];
                    float f3 = ((const float*)&b3)[j];
                    uint64_t bb0 = pack2(f0, f0);
                    uint64_t bb1 = pack2(f1, f1);
                    uint64_t bb2 = pack2(f2, f2);
                    uint64_t bb3 = pack2(f3, f3);
                    ffma2(acc[0],  a01.x, bb0); ffma2(acc[1],  a01.y, bb0);
                    ffma2(acc[2],  a23.x, bb0); ffma2(acc[3],  a23.y, bb0);
                    ffma2(acc[4],  a01.x, bb1); ffma2(acc[5],  a01.y, bb1);
                    ffma2(acc[6],  a23.x, bb1); ffma2(acc[7],  a23.y, bb1);
                    ffma2(acc[8],  a01.x, bb2); ffma2(acc[9],  a01.y, bb2);
                    ffma2(acc[10], a23.x, bb2); ffma2(acc[11], a23.y, bb2);
                    ffma2(acc[12], a01.x, bb3); ffma2(acc[13], a01.y, bb3);
                    ffma2(acc[14], a23.x, bb3); ffma2(acc[15], a23.y, bb3);
                }
            }
        }
        __syncthreads();

        // ================= combine K-partitions + epilogue ===================
        // q -> output pair base: o = rg*8 + (q>>1)*4 + (q&1)*2
        float* ex  = Bsh;            // [64 pix][66]: kp1 partials, [pix][o]
        float* osh = Bsh + 4352;     // [64 o][65]: final values for store

        if (kp == 1) {
            #pragma unroll
            for (int p = 0; p < 4; p++) {
                int pix = cg*4 + p;
                #pragma unroll
                for (int q = 0; q < 4; q++) {
                    int o = rg*8 + (q >> 1)*4 + (q & 1)*2;
                    *(uint64_t*)&ex[pix*66 + o] = acc[p*4 + q];
                }
            }
        }
        __syncthreads();
        if (kp == 0) {
            #pragma unroll
            for (int p = 0; p < 4; p++) {
                int pix = cg*4 + p;
                #pragma unroll
                for (int q = 0; q < 4; q++) {
                    int o = rg*8 + (q >> 1)*4 + (q & 1)*2;
                    int jj = (q >> 1)*4 + (q & 1)*2;
                    float px, py, vx, vy;
                    unpack2(vx, vy, acc[p*4 + q]);
                    unpack2(px, py, *(const uint64_t*)&ex[pix*66 + o]);
                    vx += px + bd[jj];
                    vy += py + bd[jj+1];
                    s8[jj]   += vx; q8[jj]   += vx*vx;
                    s8[jj+1] += vy; q8[jj+1] += vy*vy;
                    osh[o*65 + pix]     = vx;
                    osh[(o+1)*65 + pix] = vy;
                }
            }
        }
        __syncthreads();

        // coalesced NCHW store of the 64x64 tile
        int obase = (b*C_*H_ + h)*W_ + w0;
        #pragma unroll
        for (int rep = 0; rep < 16; rep++) {
            int idx = rep*256 + tid;
            int o = idx >> 6, wl = idx & 63;
            out[obase + o*H_*W_ + wl] = osh[o*65 + wl];
        }
        __syncthreads();
    }

    // ---- deterministic per-block BN partials (kp0 threads hold all sums) ----
    if (kp == 0) {
        #pragma unroll
        for (int jj = 0; jj < 8; jj++) {
            int o = rg*8 + jj;
            Bsh[o*16 + cg]        = s8[jj];
            Bsh[1024 + o*16 + cg] = q8[jj];
        }
    }
    __syncthreads();
    if (tid < 128) {
        int o = tid & 63, sel = tid >> 6;
        const float* src = Bsh + sel*1024 + o*16;
        float s = 0.f;
        #pragma unroll
        for (int w = 0; w < 16; w++) s += src[w];
        g_part[blockIdx.x*128 + sel*64 + o] = s;
    }
}

// ------------------------------------------------------ BN stats -> affine A,B
__global__ void k_stats(const float* __restrict__ gamma,
                        const float* __restrict__ beta) {
    int o = blockIdx.x;
    int tid = threadIdx.x;
    __shared__ float rs[256], rq[256];
    float s = 0.f, q = 0.f;
    for (int j = tid; j < MAIN_BLOCKS; j += 256) {
        s += g_part[j*128 + o];
        q += g_part[j*128 + 64 + o];
    }
    rs[tid] = s; rq[tid] = q;
    __syncthreads();
    for (int st = 128; st > 0; st >>= 1) {
        if (tid < st) { rs[tid] += rs[tid+st]; rq[tid] += rq[tid+st]; }
        __syncthreads();
    }
    if (tid == 0) {
        float n = (float)NPIX;
        float mean = rs[0]/n;
        float var  = rq[0]/n - mean*mean;
        float inv  = rsqrtf(var + 1e-5f);
        float A = gamma[o]*inv;
        g_ab[o]      = A;
        g_ab[64 + o] = beta[o] - mean*A;
    }
}

// -------------------------------------------------------- normalize + ReLU
__global__ void k_norm(float* __restrict__ out) {
    int i = blockIdx.x*256 + threadIdx.x;     // float4 index
    int o = (i >> 14) & 63;                   // (i*4 / 65536) % 64
    float A = g_ab[o], Bv = g_ab[64 + o];
    float4 v = ((float4*)out)[i];
    v.x = fmaxf(fmaf(v.x, A, Bv), 0.f);
    v.y = fmaxf(fmaf(v.y, A, Bv), 0.f);
    v.z = fmaxf(fmaf(v.z, A, Bv), 0.f);
    v.w = fmaxf(fmaf(v.w, A, Bv), 0.f);
    ((float4*)out)[i] = v;
}

extern "C" void kernel_launch(void* const* d_in, const int* in_sizes, int n_in,
                              void* d_out, int out_size) {
    const float* x     = (const float*)d_in[0];
    const float* w_off = (const float*)d_in[1];
    const float* b_off = (const float*)d_in[2];
    const float* w_dcn = (const float*)d_in[3];
    const float* b_dcn = (const float*)d_in[4];
    const float* gamma = (const float*)d_in[5];
    const float* beta  = (const float*)d_in[6];
    float* out = (float*)d_out;

    cudaFuncSetAttribute(k_main, cudaFuncAttributeMaxDynamicSharedMemorySize, SMEM_BYTES);

    k_zero_pad<<<1024, 256>>>();
    k_transpose<<<dim3(8, 2, B_*H_), dim3(32, 8)>>>(x);
    k_offset<<<1024, 256>>>(x, w_off, b_off);
    k_main<<<MAIN_BLOCKS, 256, SMEM_BYTES>>>(w_dcn, b_dcn, out);
    k_stats<<<64, 256>>>(gamma, beta);
    k_norm<<<NPIX*C_/4/256, 256>>>(out);
}

// round 7
// speedup vs baseline: 1.1452x; 1.0099x over previous
#include <cuda_runtime.h>
#include <math.h>
#include <stdint.h>

#define B_ 8
#define C_ 64
#define H_ 256
#define W_ 256
#define HP 258
#define NPIX (B_*H_*W_)          // 524288
#define MAIN_BLOCKS 2048
// smem: Ash 192*64 + Bsh 64*196 + meta 608
#define ASH_FLOATS (192*64)
#define BSH_FLOATS (64*196)
#define META_FLOATS 608
#define SMEM_FLOATS (ASH_FLOATS + BSH_FLOATS + META_FLOATS)
#define SMEM_BYTES (SMEM_FLOATS * 4)

// ---- device scratch (allocation-free rule: static __device__ globals) ----
__device__ float g_xt[B_*HP*W_*C_];     // padded, channel-last input  ~135 MB
__device__ float g_om[NPIX*9];          // offsets+mask logits, [b][h][w][9]
__device__ float g_part[MAIN_BLOCKS*128]; // per-block BN partials (sum, sumsq)
__device__ float g_ab[128];             // A[o], B[o] affine for BN epilogue

// ---- f32x2 helpers (ptxas never auto-fuses FFMA2) ----
__device__ __forceinline__ void ffma2(uint64_t& d, uint64_t a, uint64_t b) {
    asm("fma.rn.f32x2 %0, %1, %2, %3;" : "=l"(d) : "l"(a), "l"(b), "l"(d));
}
__device__ __forceinline__ uint64_t pack2(float lo, float hi) {
    uint64_t r;
    asm("mov.b64 %0, {%1, %2};" : "=l"(r) : "f"(lo), "f"(hi));
    return r;
}
__device__ __forceinline__ void unpack2(float& lo, float& hi, uint64_t v) {
    asm("mov.b64 {%0, %1}, %2;" : "=f"(lo), "=f"(hi) : "l"(v));
}

// ---------------------------------------------------------------- zero pad rows
__global__ void k_zero_pad() {
    int i = blockIdx.x*256 + threadIdx.x;      // 262144 total
    int b = i >> 15;
    int r = (i >> 14) & 1;
    int j = i & 16383;                          // w*64 + c
    g_xt[(b*HP + r*257)*(W_*C_) + j] = 0.f;
}

// ------------------------------------------------- NCHW -> padded channel-last
__global__ void k_transpose(const float* __restrict__ x) {
    __shared__ float tile[32][33];
    int wb = blockIdx.x*32, cb = blockIdx.y*32;
    int b = blockIdx.z >> 8, h = blockIdx.z & 255;
    int tx = threadIdx.x, ty = threadIdx.y;
    #pragma unroll
    for (int i = 0; i < 4; i++) {
        int c = cb + ty + 8*i;
        tile[ty+8*i][tx] = x[((b*C_ + c)*H_ + h)*W_ + wb + tx];
    }
    __syncthreads();
    #pragma unroll
    for (int i = 0; i < 4; i++) {
        int w = wb + ty + 8*i;
        g_xt[((b*HP + h + 1)*W_ + w)*C_ + cb + tx] = tile[tx][ty+8*i];
    }
}

// --------------------------------------------------- offset conv (9 ch, 3x1)
__global__ void k_offset(const float* __restrict__ x,
                         const float* __restrict__ w_off,
                         const float* __restrict__ b_off) {
    __shared__ float wo[1728];
    int tid = threadIdx.x;
    for (int i = tid; i < 1728; i += 256) wo[i] = w_off[i];
    __syncthreads();
    int pix0 = blockIdx.x*512 + tid;
    int pix1 = pix0 + 256;
    int b  = pix0 >> 16;
    int h0 = (pix0 >> 8) & 255, w0 = pix0 & 255;
    int h1 = (pix1 >> 8) & 255, w1 = pix1 & 255;
    float a0[9], a1[9];
    #pragma unroll
    for (int o = 0; o < 9; o++) { a0[o] = b_off[o]; a1[o] = a0[o]; }
    const float* xb = x + b*C_*H_*W_;
    for (int c = 0; c < C_; c++) {
        const float* xc = xb + c*H_*W_;
        float v0[3], v1[3];
        #pragma unroll
        for (int dh = 0; dh < 3; dh++) {
            int r0 = h0 - 1 + dh;
            int r1 = h1 - 1 + dh;
            v0[dh] = (r0 >= 0 && r0 < H_) ? xc[r0*W_ + w0] : 0.f;
            v1[dh] = (r1 >= 0 && r1 < H_) ? xc[r1*W_ + w1] : 0.f;
        }
        #pragma unroll
        for (int o = 0; o < 9; o++) {
            const float* wp = &wo[(o*C_ + c)*3];
            a0[o] += v0[0]*wp[0] + v0[1]*wp[1] + v0[2]*wp[2];
            a1[o] += v1[0]*wp[0] + v1[1]*wp[1] + v1[2]*wp[2];
        }
    }
    #pragma unroll
    for (int o = 0; o < 9; o++) {
        g_om[pix0*9 + o] = a0[o];
        g_om[pix1*9 + o] = a1[o];
    }
}

// ------------------------------------------------------------- main DCN kernel
// Per 64-pixel tile:
//   stage om -> meta smem; gather: warp iter handles 2 taps, half-warp per tap,
//   lane&15 owns 4 channels (LDG.128 corners, 2x ffma2 each, one STS.128 per
//   2 taps into XOR-swizzled Bsh[pix][192]); register-tiled f32x2 GEMM
//   out[64 o][64 pix], thread tile 8 outputs x 4 pixels, K split in 2 halves.
__global__ void __launch_bounds__(256, 2)
k_main(const float* __restrict__ w_dcn,
       const float* __restrict__ b_dcn,
       float* __restrict__ out) {
    extern __shared__ float sm[];
    float* Ash  = sm;                       // [192][64], col = half*32+rg*4+cc
    float* Bsh  = sm + ASH_FLOATS;          // [64 pix][196], chunk-swizzled
    float* meta = sm + ASH_FLOATS + BSH_FLOATS;  // [9 ch][66 pix]

    const float* __restrict__ xt = g_xt;
    const float* __restrict__ om = g_om;

    int tid = threadIdx.x;
    int lane = tid & 31, wid = tid >> 5;

    // ---- load A: Ash[k][half*32 + rg*4 + cc] = w_dcn[o][c][kk], o=rg*8+half*4+cc
    for (int i = tid; i < ASH_FLOATS; i += 256) {
        int k    = i >> 6;
        int col  = i & 63;
        int half = col >> 5;
        int rg   = (col >> 2) & 7;
        int cc   = col & 3;
        int o    = rg*8 + half*4 + cc;
        int c    = k & 63, kk = k >> 6;
        Ash[i] = w_dcn[(o*C_ + c)*3 + kk];
    }

    // ---- GEMM thread coords
    int kp = tid >> 7;          // K-partition: 0 -> k[0,96), 1 -> k[96,192)
    int tl = tid & 127;
    int rg = tl & 7;            // output row-group (8 outputs each)
    int cg = tl >> 3;           // pixel col-group (4 pixels each), 0..15

    float bd[8];
    #pragma unroll
    for (int jj = 0; jj < 8; jj++) bd[jj] = b_dcn[rg*8 + jj];
    float s8[8], q8[8];
    #pragma unroll
    for (int jj = 0; jj < 8; jj++) { s8[jj] = 0.f; q8[jj] = 0.f; }

    // ---- gather coords
    int gh = lane >> 4;         // half: tap select
    int c4 = lane & 15;         // channel group: channels 4*c4 .. 4*c4+3

    __syncthreads();

    for (int t = 0; t < 4; t++) {
        int tileIdx = blockIdx.x*4 + t;
        int pixbase = tileIdx*64;
        int b  = pixbase >> 16;
        int h  = (pixbase >> 8) & 255;
        int w0 = pixbase & 255;

        // ================= stage om -> meta (sigmoid applied) =================
        for (int i = tid; i < 576; i += 256) {
            int pix = i / 9, ch = i - pix*9;
            float v = om[pixbase*9 + i];
            if (ch >= 6) v = 1.f/(1.f + __expf(-v));
            meta[ch*66 + pix] = v;
        }
        __syncthreads();

        // ================= gather: 192 taps -> Bsh[pix][k] ====================
        #pragma unroll
        for (int it = 0; it < 12; it++) {
            int tap  = wid*24 + it*2 + gh;
            int kk   = tap >> 6;
            int pixg = tap & 63;
            int wxp  = w0 + pixg;
            float dy = meta[kk*66 + pixg];
            float dx = meta[(3+kk)*66 + pixg];
            float mv = meta[(6+kk)*66 + pixg];
            float y  = (float)(h + kk) + dy;
            float xf = (float)wxp + dx;
            float y0 = floorf(y), x0 = floorf(xf);
            float fy = y - y0, fx = xf - x0;
            int iy0 = (int)y0, ix0 = (int)x0;
            int iy1 = iy0 + 1, ix1 = ix0 + 1;
            bool vy0 = (iy0 >= 0) && (iy0 <= HP-1);
            bool vy1 = (iy1 >= 0) && (iy1 <= HP-1);
            bool vx0 = (ix0 >= 0) && (ix0 <= W_-1);
            bool vx1 = (ix1 >= 0) && (ix1 <= W_-1);
            float gy0 = 1.f - fy, gx0 = 1.f - fx;
            float q00 = gy0*gx0*mv; if (!(vy0 && vx0)) q00 = 0.f;
            float q01 = gy0*fx*mv;  if (!(vy0 && vx1)) q01 = 0.f;
            float q10 = fy*gx0*mv;  if (!(vy1 && vx0)) q10 = 0.f;
            float q11 = fy*fx*mv;   if (!(vy1 && vx1)) q11 = 0.f;
            int cy0 = min(max(iy0,0),HP-1), cy1 = min(max(iy1,0),HP-1);
            int cx0 = min(max(ix0,0),W_-1), cx1 = min(max(ix1,0),W_-1);
            int rb = b*HP;
            ulonglong2 u00 = *((const ulonglong2*)(xt + ((rb+cy0)*W_+cx0)*C_) + c4);
            ulonglong2 u01 = *((const ulonglong2*)(xt + ((rb+cy0)*W_+cx1)*C_) + c4);
            ulonglong2 u10 = *((const ulonglong2*)(xt + ((rb+cy1)*W_+cx0)*C_) + c4);
            ulonglong2 u11 = *((const ulonglong2*)(xt + ((rb+cy1)*W_+cx1)*C_) + c4);
            uint64_t a01 = 0ull, a23 = 0ull;
            uint64_t pp;
            pp = pack2(q00, q00); ffma2(a01, u00.x, pp); ffma2(a23, u00.y, pp);
            pp = pack2(q01, q01); ffma2(a01, u01.x, pp); ffma2(a23, u01.y, pp);
            pp = pack2(q10, q10); ffma2(a01, u10.x, pp); ffma2(a23, u10.y, pp);
            pp = pack2(q11, q11); ffma2(a01, u11.x, pp); ffma2(a23, u11.y, pp);
            int key   = (pixg >> 2) & 3;
            int chunk = (kk*16 + c4) ^ key;
            *(ulonglong2*)(Bsh + pixg*196 + chunk*4) = make_ulonglong2(a01, a23);
        }
        __syncthreads();

        // ================= GEMM (f32x2), each thread 8 out x 4 pix ===========
        uint64_t acc[16];   // acc[p*4+q] = pair {o=rg*8+2q, o+1} for pixel p
        #pragma unroll
        for (int i = 0; i < 16; i++) acc[i] = 0ull;

        {
            const float* Ap = Ash + (kp*96)*64 + rg*4;
            const float* B0 = Bsh + (cg*4+0)*196;
            const float* B1 = Bsh + (cg*4+1)*196;
            const float* B2 = Bsh + (cg*4+2)*196;
            const float* B3 = Bsh + (cg*4+3)*196;
            int key = cg & 3;   // (pix>>2)&3, same for all 4 pixels of thread
            #pragma unroll 2
            for (int kb = 0; kb < 96; kb += 4) {
                int ch = ((kp*96 + kb) >> 2) ^ key;
                float4 b0 = *(const float4*)(B0 + (ch << 2));
                float4 b1 = *(const float4*)(B1 + (ch << 2));
                float4 b2 = *(const float4*)(B2 + (ch << 2));
                float4 b3 = *(const float4*)(B3 + (ch << 2));
                #pragma unroll
                for (int j = 0; j < 4; j++) {
                    const float* Ak = Ap + (kb + j)*64;
                    ulonglong2 a01 = *(const ulonglong2*)(Ak);
                    ulonglong2 a23 = *(const ulonglong2*)(Ak + 32);
                    float f0 = ((const float*)&b0)[j];
                    float f1 = ((const float*)&b1)[j];
                    float f2 = ((const float*)&b2)[j];
                    float f3 = ((const float*)&b3)[j];
                    uint64_t bb0 = pack2(f0, f0);
                    uint64_t bb1 = pack2(f1, f1);
                    uint64_t bb2 = pack2(f2, f2);
                    uint64_t bb3 = pack2(f3, f3);
                    ffma2(acc[0],  a01.x, bb0); ffma2(acc[1],  a01.y, bb0);
                    ffma2(acc[2],  a23.x, bb0); ffma2(acc[3],  a23.y, bb0);
                    ffma2(acc[4],  a01.x, bb1); ffma2(acc[5],  a01.y, bb1);
                    ffma2(acc[6],  a23.x, bb1); ffma2(acc[7],  a23.y, bb1);
                    ffma2(acc[8],  a01.x, bb2); ffma2(acc[9],  a01.y, bb2);
                    ffma2(acc[10], a23.x, bb2); ffma2(acc[11], a23.y, bb2);
                    ffma2(acc[12], a01.x, bb3); ffma2(acc[13], a01.y, bb3);
                    ffma2(acc[14], a23.x, bb3); ffma2(acc[15], a23.y, bb3);
                }
            }
        }
        __syncthreads();

        // ================= combine K-partitions + epilogue ===================
        // q -> output pair base: o = rg*8 + (q>>1)*4 + (q&1)*2
        float* ex  = Bsh;            // [64 pix][66]: kp1 partials, [pix][o]
        float* osh = Bsh + 4352;     // [64 o][65]: final values for store

        if (kp == 1) {
            #pragma unroll
            for (int p = 0; p < 4; p++) {
                int pix = cg*4 + p;
                #pragma unroll
                for (int q = 0; q < 4; q++) {
                    int o = rg*8 + (q >> 1)*4 + (q & 1)*2;
                    *(uint64_t*)&ex[pix*66 + o] = acc[p*4 + q];
                }
            }
        }
        __syncthreads();
        if (kp == 0) {
            #pragma unroll
            for (int p = 0; p < 4; p++) {
                int pix = cg*4 + p;
                #pragma unroll
                for (int q = 0; q < 4; q++) {
                    int o = rg*8 + (q >> 1)*4 + (q & 1)*2;
                    int jj = (q >> 1)*4 + (q & 1)*2;
                    float px, py, vx, vy;
                    unpack2(vx, vy, acc[p*4 + q]);
                    unpack2(px, py, *(const uint64_t*)&ex[pix*66 + o]);
                    vx += px + bd[jj];
                    vy += py + bd[jj+1];
                    s8[jj]   += vx; q8[jj]   += vx*vx;
                    s8[jj+1] += vy; q8[jj+1] += vy*vy;
                    osh[o*65 + pix]     = vx;
                    osh[(o+1)*65 + pix] = vy;
                }
            }
        }
        __syncthreads();

        // coalesced NCHW store of the 64x64 tile
        int obase = (b*C_*H_ + h)*W_ + w0;
        #pragma unroll
        for (int rep = 0; rep < 16; rep++) {
            int idx = rep*256 + tid;
            int o = idx >> 6, wl = idx & 63;
            out[obase + o*H_*W_ + wl] = osh[o*65 + wl];
        }
        __syncthreads();
    }

    // ---- deterministic per-block BN partials (kp0 threads hold all sums) ----
    if (kp == 0) {
        #pragma unroll
        for (int jj = 0; jj < 8; jj++) {
            int o = rg*8 + jj;
            Bsh[o*16 + cg]        = s8[jj];
            Bsh[1024 + o*16 + cg] = q8[jj];
        }
    }
    __syncthreads();
    if (tid < 128) {
        int o = tid & 63, sel = tid >> 6;
        const float* src = Bsh + sel*1024 + o*16;
        float s = 0.f;
        #pragma unroll
        for (int w = 0; w < 16; w++) s += src[w];
        g_part[blockIdx.x*128 + sel*64 + o] = s;
    }
}

// ------------------------------------------------------ BN stats -> affine A,B
__global__ void k_stats(const float* __restrict__ gamma,
                        const float* __restrict__ beta) {
    int o = blockIdx.x;
    int tid = threadIdx.x;
    __shared__ float rs[256], rq[256];
    float s = 0.f, q = 0.f;
    for (int j = tid; j < MAIN_BLOCKS; j += 256) {
        s += g_part[j*128 + o];
        q += g_part[j*128 + 64 + o];
    }
    rs[tid] = s; rq[tid] = q;
    __syncthreads();
    for (int st = 128; st > 0; st >>= 1) {
        if (tid < st) { rs[tid] += rs[tid+st]; rq[tid] += rq[tid+st]; }
        __syncthreads();
    }
    if (tid == 0) {
        float n = (float)NPIX;
        float mean = rs[0]/n;
        float var  = rq[0]/n - mean*mean;
        float inv  = rsqrtf(var + 1e-5f);
        float A = gamma[o]*inv;
        g_ab[o]      = A;
        g_ab[64 + o] = beta[o] - mean*A;
    }
}

// -------------------------------------------------------- normalize + ReLU
__global__ void k_norm(float* __restrict__ out) {
    int i = blockIdx.x*256 + threadIdx.x;     // float4 index
    int o = (i >> 14) & 63;                   // (i*4 / 65536) % 64
    float A = g_ab[o], Bv = g_ab[64 + o];
    float4 v = ((float4*)out)[i];
    v.x = fmaxf(fmaf(v.x, A, Bv), 0.f);
    v.y = fmaxf(fmaf(v.y, A, Bv), 0.f);
    v.z = fmaxf(fmaf(v.z, A, Bv), 0.f);
    v.w = fmaxf(fmaf(v.w, A, Bv), 0.f);
    ((float4*)out)[i] = v;
}

extern "C" void kernel_launch(void* const* d_in, const int* in_sizes, int n_in,
                              void* d_out, int out_size) {
    const float* x     = (const float*)d_in[0];
    const float* w_off = (const float*)d_in[1];
    const float* b_off = (const float*)d_in[2];
    const float* w_dcn = (const float*)d_in[3];
    const float* b_dcn = (const float*)d_in[4];
    const float* gamma = (const float*)d_in[5];
    const float* beta  = (const float*)d_in[6];
    float* out = (float*)d_out;

    cudaFuncSetAttribute(k_main, cudaFuncAttributeMaxDynamicSharedMemorySize, SMEM_BYTES);

    k_zero_pad<<<1024, 256>>>();
    k_transpose<<<dim3(8, 2, B_*H_), dim3(32, 8)>>>(x);
    k_offset<<<1024, 256>>>(x, w_off, b_off);
    k_main<<<MAIN_BLOCKS, 256, SMEM_BYTES>>>(w_dcn, b_dcn, out);
    k_stats<<<64, 256>>>(gamma, beta);
    k_norm<<<NPIX*C_/4/256, 256>>>(out);
}

// round 10
// speedup vs baseline: 1.7911x; 1.5641x over previous
#include <cuda_runtime.h>
#include <cuda_fp16.h>
#include <math.h>
#include <stdint.h>

#define B_ 8
#define C_ 64
#define H_ 256
#define W_ 256
#define HP 258
#define NPIX (B_*H_*W_)          // 524288
#define MAIN_BLOCKS 1024         // 4096 tiles of 128 pixels, 4 per block

// ---- smem layout (bytes). fp16 rows are 192 halves = 384 B; stride 400 B. ----
#define WROW 400
#define WHF_OFF   0                         // [64 o][400B]  fp16 weights
#define WHF_BYTES (64*WROW)                 // 25600
#define SHF_OFF   (WHF_OFF + WHF_BYTES)     // [128 px][400B] fp16 sampled
#define SHF_BYTES (128*WROW)                // 51200
#define META_OFF  (SHF_OFF + SHF_BYTES)     // [9][132] f32
#define META_BYTES (9*132*4)                // 4752
#define BIAS_OFF  (META_OFF + META_BYTES)   // 64 f32
#define SMEM_BYTES (BIAS_OFF + 256 + 256)
// osh [64 o][132] f32 (33792 B) overlays Shf after the GEMM phase.

// ---- device scratch ----
__device__ float g_xt[B_*HP*W_*C_];     // padded channel-last input
__device__ float g_om[NPIX*9];          // offsets+mask logits
__device__ float g_part[MAIN_BLOCKS*128];
__device__ float g_ab[128];

// ---- helpers ----
__device__ __forceinline__ void ffma2(uint64_t& d, uint64_t a, uint64_t b) {
    asm("fma.rn.f32x2 %0, %1, %2, %3;" : "=l"(d) : "l"(a), "l"(b), "l"(d));
}
__device__ __forceinline__ uint64_t pack2(float lo, float hi) {
    uint64_t r; asm("mov.b64 %0, {%1, %2};" : "=l"(r) : "f"(lo), "f"(hi)); return r;
}
__device__ __forceinline__ void unpack2(float& lo, float& hi, uint64_t v) {
    asm("mov.b64 {%0, %1}, %2;" : "=f"(lo), "=f"(hi) : "l"(v));
}
__device__ __forceinline__ void mma16816(float& c0, float& c1, float& c2, float& c3,
                                         uint32_t a0, uint32_t a1, uint32_t a2, uint32_t a3,
                                         uint32_t b0, uint32_t b1) {
    asm volatile(
        "mma.sync.aligned.m16n8k16.row.col.f32.f16.f16.f32 "
        "{%0,%1,%2,%3}, {%4,%5,%6,%7}, {%8,%9}, {%0,%1,%2,%3};"
        : "+f"(c0), "+f"(c1), "+f"(c2), "+f"(c3)
        : "r"(a0), "r"(a1), "r"(a2), "r"(a3), "r"(b0), "r"(b1));
}
__device__ __forceinline__ uint32_t h2u(float lo, float hi) {
    __half2 h = __floats2half2_rn(lo, hi);
    return *(uint32_t*)&h;
}

// ---------------------------------------------------------------- zero pad rows
__global__ void k_zero_pad() {
    int i = blockIdx.x*256 + threadIdx.x;
    int b = i >> 15;
    int r = (i >> 14) & 1;
    int j = i & 16383;
    g_xt[(b*HP + r*257)*(W_*C_) + j] = 0.f;
}

// ------------------------------------------------- NCHW -> padded channel-last
__global__ void k_transpose(const float* __restrict__ x) {
    __shared__ float tile[32][33];
    int wb = blockIdx.x*32, cb = blockIdx.y*32;
    int b = blockIdx.z >> 8, h = blockIdx.z & 255;
    int tx = threadIdx.x, ty = threadIdx.y;
    #pragma unroll
    for (int i = 0; i < 4; i++) {
        int c = cb + ty + 8*i;
        tile[ty+8*i][tx] = x[((b*C_ + c)*H_ + h)*W_ + wb + tx];
    }
    __syncthreads();
    #pragma unroll
    for (int i = 0; i < 4; i++) {
        int w = wb + ty + 8*i;
        g_xt[((b*HP + h + 1)*W_ + w)*C_ + cb + tx] = tile[tx][ty+8*i];
    }
}

// --------------------------------------------------- offset conv (9 ch, 3x1)
__global__ void k_offset(const float* __restrict__ x,
                         const float* __restrict__ w_off,
                         const float* __restrict__ b_off) {
    __shared__ float wo[1728];
    int tid = threadIdx.x;
    for (int i = tid; i < 1728; i += 256) wo[i] = w_off[i];
    __syncthreads();
    int pix0 = blockIdx.x*512 + tid;
    int pix1 = pix0 + 256;
    int b  = pix0 >> 16;
    int h0 = (pix0 >> 8) & 255, w0 = pix0 & 255;
    int h1 = (pix1 >> 8) & 255, w1 = pix1 & 255;
    float a0[9], a1[9];
    #pragma unroll
    for (int o = 0; o < 9; o++) { a0[o] = b_off[o]; a1[o] = a0[o]; }
    const float* xb = x + b*C_*H_*W_;
    for (int c = 0; c < C_; c++) {
        const float* xc = xb + c*H_*W_;
        float v0[3], v1[3];
        #pragma unroll
        for (int dh = 0; dh < 3; dh++) {
            int r0 = h0 - 1 + dh;
            int r1 = h1 - 1 + dh;
            v0[dh] = (r0 >= 0 && r0 < H_) ? xc[r0*W_ + w0] : 0.f;
            v1[dh] = (r1 >= 0 && r1 < H_) ? xc[r1*W_ + w1] : 0.f;
        }
        #pragma unroll
        for (int o = 0; o < 9; o++) {
            const float* wp = &wo[(o*C_ + c)*3];
            a0[o] += v0[0]*wp[0] + v0[1]*wp[1] + v0[2]*wp[2];
            a1[o] += v1[0]*wp[0] + v1[1]*wp[1] + v1[2]*wp[2];
        }
    }
    #pragma unroll
    for (int o = 0; o < 9; o++) {
        g_om[pix0*9 + o] = a0[o];
        g_om[pix1*9 + o] = a1[o];
    }
}

// ------------------------------------------------------------- main DCN kernel
// Per 128-pixel tile: gather (f32 bilinear, fp16 output) -> Shf[px][192];
// GEMM out[64 o][128 px] via mma.sync.m16n8k16 fp16, fp32 accum.
// Warp w: outputs 16*(w&3)..+15, pixels 64*(w>>2)..+63. W frags preloaded.
__global__ void __launch_bounds__(256, 2)
k_main(const float* __restrict__ w_dcn,
       const float* __restrict__ b_dcn,
       float* __restrict__ out) {
    extern __shared__ char smem[];
    char*   Shf  = smem + SHF_OFF;
    float*  meta = (float*)(smem + META_OFF);
    float*  bias = (float*)(smem + BIAS_OFF);
    float*  osh  = (float*)(smem + SHF_OFF);   // overlay, valid post-GEMM

    const float* __restrict__ xt = g_xt;
    const float* __restrict__ om = g_om;

    int tid = threadIdx.x;
    int lane = tid & 31, wid = tid >> 5;
    int g  = lane >> 2;         // mma group id (0-7)
    int tg = lane & 3;          // thread-in-group

    // ---- fill Whf[o][k] fp16 (row stride 400 B) + bias
    for (int i = tid; i < 64*192; i += 256) {
        int o = i / 192, k = i - o*192;
        int c = k & 63, kk = k >> 6;
        *(__half*)(smem + WHF_OFF + o*WROW + k*2) =
            __float2half_rn(w_dcn[(o*C_ + c)*3 + kk]);
    }
    if (tid < 64) bias[tid] = b_dcn[tid];
    __syncthreads();

    // ---- warp tile coords
    int obase  = (wid & 3) * 16;
    int pxbase = (wid >> 2) * 64;

    // ---- preload W fragments: aW[kt][0..3]
    uint32_t aW[12][4];
    {
        const char* wrow0 = smem + WHF_OFF + (obase + g)*WROW     + tg*4;
        const char* wrow8 = smem + WHF_OFF + (obase + 8 + g)*WROW + tg*4;
        #pragma unroll
        for (int kt = 0; kt < 12; kt++) {
            aW[kt][0] = *(const uint32_t*)(wrow0 + kt*32);
            aW[kt][1] = *(const uint32_t*)(wrow8 + kt*32);
            aW[kt][2] = *(const uint32_t*)(wrow0 + kt*32 + 16);
            aW[kt][3] = *(const uint32_t*)(wrow8 + kt*32 + 16);
        }
    }
    float bia0 = bias[obase + g];
    float bia8 = bias[obase + 8 + g];

    int gh = lane >> 4;         // gather: tap select in pair
    int c4 = lane & 15;         // gather: channel group (4 channels)

    float sAcc = 0.f, qAcc = 0.f;  // per-thread BN partials

    for (int t = 0; t < 4; t++) {
        int tileIdx = blockIdx.x*4 + t;
        int pixbase = tileIdx*128;
        int b  = pixbase >> 16;
        int h  = (pixbase >> 8) & 255;
        int w0 = pixbase & 255;

        // ======== stage om -> meta (sigmoid applied) ========
        for (int i = tid; i < 1152; i += 256) {
            int pix = i / 9, ch = i - pix*9;
            float v = om[pixbase*9 + i];
            if (ch >= 6) v = 1.f/(1.f + __expf(-v));
            meta[ch*132 + pix] = v;
        }
        __syncthreads();

        // ======== gather 384 taps -> Shf[px][k] fp16 ========
        #pragma unroll 2
        for (int it = 0; it < 24; it++) {
            int tap  = wid*48 + it*2 + gh;
            int kk   = tap >> 7;
            int pixg = tap & 127;
            int wxp  = w0 + pixg;
            float dy = meta[kk*132 + pixg];
            float dx = meta[(3+kk)*132 + pixg];
            float mv = meta[(6+kk)*132 + pixg];
            float y  = (float)(h + kk) + dy;
            float xf = (float)wxp + dx;
            float y0 = floorf(y), x0 = floorf(xf);
            float fy = y - y0, fx = xf - x0;
            int iy0 = (int)y0, ix0 = (int)x0;
            int iy1 = iy0 + 1, ix1 = ix0 + 1;
            bool vy0 = (iy0 >= 0) && (iy0 <= HP-1);
            bool vy1 = (iy1 >= 0) && (iy1 <= HP-1);
            bool vx0 = (ix0 >= 0) && (ix0 <= W_-1);
            bool vx1 = (ix1 >= 0) && (ix1 <= W_-1);
            float gy0 = 1.f - fy, gx0 = 1.f - fx;
            float q00 = gy0*gx0*mv; if (!(vy0 && vx0)) q00 = 0.f;
            float q01 = gy0*fx*mv;  if (!(vy0 && vx1)) q01 = 0.f;
            float q10 = fy*gx0*mv;  if (!(vy1 && vx0)) q10 = 0.f;
            float q11 = fy*fx*mv;   if (!(vy1 && vx1)) q11 = 0.f;
            int cy0 = min(max(iy0,0),HP-1), cy1 = min(max(iy1,0),HP-1);
            int cx0 = min(max(ix0,0),W_-1), cx1 = min(max(ix1,0),W_-1);
            int rb = b*HP;
            ulonglong2 u00 = *((const ulonglong2*)(xt + ((rb+cy0)*W_+cx0)*C_) + c4);
            ulonglong2 u01 = *((const ulonglong2*)(xt + ((rb+cy0)*W_+cx1)*C_) + c4);
            ulonglong2 u10 = *((const ulonglong2*)(xt + ((rb+cy1)*W_+cx0)*C_) + c4);
            ulonglong2 u11 = *((const ulonglong2*)(xt + ((rb+cy1)*W_+cx1)*C_) + c4);
            uint64_t a01 = 0ull, a23 = 0ull;
            uint64_t pp;
            pp = pack2(q00, q00); ffma2(a01, u00.x, pp); ffma2(a23, u00.y, pp);
            pp = pack2(q01, q01); ffma2(a01, u01.x, pp); ffma2(a23, u01.y, pp);
            pp = pack2(q10, q10); ffma2(a01, u10.x, pp); ffma2(a23, u10.y, pp);
            pp = pack2(q11, q11); ffma2(a01, u11.x, pp); ffma2(a23, u11.y, pp);
            float v0, v1, v2, v3;
            unpack2(v0, v1, a01);
            unpack2(v2, v3, a23);
            uint2 hv = make_uint2(h2u(v0, v1), h2u(v2, v3));
            *(uint2*)(Shf + pixg*WROW + kk*128 + c4*8) = hv;
        }
        __syncthreads();

        // ======== GEMM: 96 mma.sync per warp ========
        float acc[8][4];
        #pragma unroll
        for (int ng = 0; ng < 8; ng++)
            #pragma unroll
            for (int j = 0; j < 4; j++) acc[ng][j] = 0.f;

        {
            const char* sBase = Shf + (pxbase + g)*WROW + tg*4;
            #pragma unroll
            for (int kt = 0; kt < 12; kt++) {
                const char* sk = sBase + kt*32;
                #pragma unroll
                for (int ng = 0; ng < 8; ng++) {
                    uint32_t b0 = *(const uint32_t*)(sk + ng*(8*WROW));
                    uint32_t b1 = *(const uint32_t*)(sk + ng*(8*WROW) + 16);
                    mma16816(acc[ng][0], acc[ng][1], acc[ng][2], acc[ng][3],
                             aW[kt][0], aW[kt][1], aW[kt][2], aW[kt][3], b0, b1);
                }
            }
        }
        __syncthreads();   // all warps done reading Shf before osh overlays it

        // ======== epilogue: acc -> osh[o][px] (+bias) ========
        {
            float* o0 = osh + (obase + g)*132     + pxbase + 2*tg;
            float* o8 = osh + (obase + 8 + g)*132 + pxbase + 2*tg;
            #pragma unroll
            for (int ng = 0; ng < 8; ng++) {
                *(float2*)(o0 + ng*8) = make_float2(acc[ng][0] + bia0, acc[ng][1] + bia0);
                *(float2*)(o8 + ng*8) = make_float2(acc[ng][2] + bia8, acc[ng][3] + bia8);
            }
        }
        __syncthreads();

        // ======== BN partials for this tile ========
        {
            int o = tid >> 2, q4 = tid & 3;
            const float* r = osh + o*132 + q4*32;
            float s = 0.f, q = 0.f;
            #pragma unroll
            for (int j = 0; j < 32; j++) { float v = r[j]; s += v; q += v*v; }
            meta[tid] = s;            // meta reused as scratch; re-staged next tile
            meta[256 + tid] = q;
        }
        __syncthreads();
        if (tid < 64) {
            sAcc += meta[tid*4] + meta[tid*4+1] + meta[tid*4+2] + meta[tid*4+3];
            qAcc += meta[256 + tid*4] + meta[256 + tid*4+1]
                  + meta[256 + tid*4+2] + meta[256 + tid*4+3];
        }

        // ======== coalesced NCHW store of 64 x 128 tile ========
        int obase2 = (b*C_*H_ + h)*W_ + w0;
        #pragma unroll
        for (int rep = 0; rep < 32; rep++) {
            int idx = rep*256 + tid;
            int o = idx >> 7, p = idx & 127;
            out[obase2 + o*H_*W_ + p] = osh[o*132 + p];
        }
        __syncthreads();
    }

    // ---- per-block BN partials ----
    if (tid < 64) {
        g_part[blockIdx.x*128 + tid]      = sAcc;
        g_part[blockIdx.x*128 + 64 + tid] = qAcc;
    }
}

// ------------------------------------------------------ BN stats -> affine A,B
__global__ void k_stats(const float* __restrict__ gamma,
                        const float* __restrict__ beta) {
    int o = blockIdx.x;
    int tid = threadIdx.x;
    __shared__ float rs[256], rq[256];
    float s = 0.f, q = 0.f;
    for (int j = tid; j < MAIN_BLOCKS; j += 256) {
        s += g_part[j*128 + o];
        q += g_part[j*128 + 64 + o];
    }
    rs[tid] = s; rq[tid] = q;
    __syncthreads();
    for (int st = 128; st > 0; st >>= 1) {
        if (tid < st) { rs[tid] += rs[tid+st]; rq[tid] += rq[tid+st]; }
        __syncthreads();
    }
    if (tid == 0) {
        float n = (float)NPIX;
        float mean = rs[0]/n;
        float var  = rq[0]/n - mean*mean;
        float inv  = rsqrtf(var + 1e-5f);
        float A = gamma[o]*inv;
        g_ab[o]      = A;
        g_ab[64 + o] = beta[o] - mean*A;
    }
}

// -------------------------------------------------------- normalize + ReLU
__global__ void k_norm(float* __restrict__ out) {
    int i = blockIdx.x*256 + threadIdx.x;
    int o = (i >> 14) & 63;
    float A = g_ab[o], Bv = g_ab[64 + o];
    float4 v = ((float4*)out)[i];
    v.x = fmaxf(fmaf(v.x, A, Bv), 0.f);
    v.y = fmaxf(fmaf(v.y, A, Bv), 0.f);
    v.z = fmaxf(fmaf(v.z, A, Bv), 0.f);
    v.w = fmaxf(fmaf(v.w, A, Bv), 0.f);
    ((float4*)out)[i] = v;
}

extern "C" void kernel_launch(void* const* d_in, const int* in_sizes, int n_in,
                              void* d_out, int out_size) {
    const float* x     = (const float*)d_in[0];
    const float* w_off = (const float*)d_in[1];
    const float* b_off = (const float*)d_in[2];
    const float* w_dcn = (const float*)d_in[3];
    const float* b_dcn = (const float*)d_in[4];
    const float* gamma = (const float*)d_in[5];
    const float* beta  = (const float*)d_in[6];
    float* out = (float*)d_out;

    cudaFuncSetAttribute(k_main, cudaFuncAttributeMaxDynamicSharedMemorySize, SMEM_BYTES);

    k_zero_pad<<<1024, 256>>>();
    k_transpose<<<dim3(8, 2, B_*H_), dim3(32, 8)>>>(x);
    k_offset<<<1024, 256>>>(x, w_off, b_off);
    k_main<<<MAIN_BLOCKS, 256, SMEM_BYTES>>>(w_dcn, b_dcn, out);
    k_stats<<<64, 256>>>(gamma, beta);
    k_norm<<<NPIX*C_/4/256, 256>>>(out);
}

// round 12
// speedup vs baseline: 2.0884x; 1.1660x over previous
#include <cuda_runtime.h>
#include <cuda_fp16.h>
#include <math.h>
#include <stdint.h>

#define B_ 8
#define C_ 64
#define H_ 256
#define W_ 256
#define HP 258
#define NPIX (B_*H_*W_)          // 524288
#define MAIN_BLOCKS 1024         // 4096 tiles of 128 pixels, 4 per block

// ---- smem layout (bytes). fp16 rows are 192 halves = 384 B; stride 400 B. ----
#define WROW 400
#define WHF_OFF   0                         // [64 o][400B]  fp16 weights
#define WHF_BYTES (64*WROW)                 // 25600
#define WOF_OFF   (WHF_OFF + WHF_BYTES)     // [16 oc][400B] fp16 offset-conv W
#define WOF_BYTES (16*WROW)                 // 6400
#define SHF_OFF   (WOF_OFF + WOF_BYTES)     // [128 px][400B] fp16 sampled
#define SHF_BYTES (128*WROW)                // 51200
#define META_OFF  (SHF_OFF + SHF_BYTES)     // [9][132] f32
#define META_BYTES (9*132*4)                // 4752
#define BIAS_OFF  (META_OFF + META_BYTES)   // 64 f32 (dcn bias) + 16 f32 (off bias)
#define SMEM_BYTES (BIAS_OFF + 384 + 256)
// osh [64 o][132] f32 (33792 B) overlays Shf after the main GEMM phase.

// ---- device scratch ----
__device__ float g_xt[B_*HP*W_*C_];     // padded channel-last input
__device__ float g_part[MAIN_BLOCKS*128];
__device__ float g_ab[128];

// ---- helpers ----
__device__ __forceinline__ void ffma2(uint64_t& d, uint64_t a, uint64_t b) {
    asm("fma.rn.f32x2 %0, %1, %2, %3;" : "=l"(d) : "l"(a), "l"(b), "l"(d));
}
__device__ __forceinline__ uint64_t pack2(float lo, float hi) {
    uint64_t r; asm("mov.b64 %0, {%1, %2};" : "=l"(r) : "f"(lo), "f"(hi)); return r;
}
__device__ __forceinline__ void unpack2(float& lo, float& hi, uint64_t v) {
    asm("mov.b64 {%0, %1}, %2;" : "=f"(lo), "=f"(hi) : "l"(v));
}
__device__ __forceinline__ void mma16816(float& c0, float& c1, float& c2, float& c3,
                                         uint32_t a0, uint32_t a1, uint32_t a2, uint32_t a3,
                                         uint32_t b0, uint32_t b1) {
    asm volatile(
        "mma.sync.aligned.m16n8k16.row.col.f32.f16.f16.f32 "
        "{%0,%1,%2,%3}, {%4,%5,%6,%7}, {%8,%9}, {%0,%1,%2,%3};"
        : "+f"(c0), "+f"(c1), "+f"(c2), "+f"(c3)
        : "r"(a0), "r"(a1), "r"(a2), "r"(a3), "r"(b0), "r"(b1));
}
__device__ __forceinline__ uint32_t h2u(float lo, float hi) {
    __half2 h = __floats2half2_rn(lo, hi);
    return *(uint32_t*)&h;
}

// ---------------------------------------------------------------- zero pad rows
__global__ void k_zero_pad() {
    int i = blockIdx.x*256 + threadIdx.x;
    int b = i >> 15;
    int r = (i >> 14) & 1;
    int j = i & 16383;
    g_xt[(b*HP + r*257)*(W_*C_) + j] = 0.f;
}

// ------------------------------------------------- NCHW -> padded channel-last
__global__ void k_transpose(const float* __restrict__ x) {
    __shared__ float tile[32][33];
    int wb = blockIdx.x*32, cb = blockIdx.y*32;
    int b = blockIdx.z >> 8, h = blockIdx.z & 255;
    int tx = threadIdx.x, ty = threadIdx.y;
    #pragma unroll
    for (int i = 0; i < 4; i++) {
        int c = cb + ty + 8*i;
        tile[ty+8*i][tx] = x[((b*C_ + c)*H_ + h)*W_ + wb + tx];
    }
    __syncthreads();
    #pragma unroll
    for (int i = 0; i < 4; i++) {
        int w = wb + ty + 8*i;
        g_xt[((b*HP + h + 1)*W_ + w)*C_ + cb + tx] = tile[tx][ty+8*i];
    }
}

// ------------------------------------------------------------- main DCN kernel
// Per 128-pixel tile:
//  1. stage S0[px][192] = xt rows h-1..h+1 (fp16) into Shf
//  2. om[9][128] = Wof x S0^T via mma (fp32 accum) -> meta (+bias, sigmoid)
//  3. gather with bilinear offsets -> Shf (overwrite)
//  4. out[64 o][128 px] = Wdcn x Shf^T via mma
// Warp w: outputs 16*(w&3)..+15, pixels 64*(w>>2)..+63 for main GEMM.
__global__ void __launch_bounds__(256, 2)
k_main(const float* __restrict__ w_dcn,
       const float* __restrict__ b_dcn,
       const float* __restrict__ w_off,
       const float* __restrict__ b_off,
       float* __restrict__ out) {
    extern __shared__ char smem[];
    char*   Shf  = smem + SHF_OFF;
    float*  meta = (float*)(smem + META_OFF);
    float*  bias = (float*)(smem + BIAS_OFF);       // [64] dcn bias
    float*  obias = (float*)(smem + BIAS_OFF + 256); // [16] offset-conv bias
    float*  osh  = (float*)(smem + SHF_OFF);        // overlay, valid post-GEMM

    const float* __restrict__ xt = g_xt;

    int tid = threadIdx.x;
    int lane = tid & 31, wid = tid >> 5;
    int g  = lane >> 2;         // mma group id (0-7)
    int tg = lane & 3;          // thread-in-group

    // ---- fill Whf[o][k] fp16 (row stride 400 B)
    for (int i = tid; i < 64*192; i += 256) {
        int o = i / 192, k = i - o*192;
        int c = k & 63, kk = k >> 6;
        *(__half*)(smem + WHF_OFF + o*WROW + k*2) =
            __float2half_rn(w_dcn[(o*C_ + c)*3 + kk]);
    }
    // ---- fill Wof[oc][k] fp16, rows 9..15 zero
    for (int i = tid; i < 16*192; i += 256) {
        int o = i / 192, k = i - o*192;
        int c = k & 63, kk = k >> 6;
        float v = (o < 9) ? w_off[(o*C_ + c)*3 + kk] : 0.f;
        *(__half*)(smem + WOF_OFF + o*WROW + k*2) = __float2half_rn(v);
    }
    if (tid < 64) bias[tid] = b_dcn[tid];
    if (tid >= 64 && tid < 80) obias[tid-64] = (tid-64 < 9) ? b_off[tid-64] : 0.f;
    __syncthreads();

    // ---- warp tile coords (main GEMM)
    int obase  = (wid & 3) * 16;
    int pxbase = (wid >> 2) * 64;

    // ---- preload W fragments: aW[kt][0..3]
    uint32_t aW[12][4];
    {
        const char* wrow0 = smem + WHF_OFF + (obase + g)*WROW     + tg*4;
        const char* wrow8 = smem + WHF_OFF + (obase + 8 + g)*WROW + tg*4;
        #pragma unroll
        for (int kt = 0; kt < 12; kt++) {
            aW[kt][0] = *(const uint32_t*)(wrow0 + kt*32);
            aW[kt][1] = *(const uint32_t*)(wrow8 + kt*32);
            aW[kt][2] = *(const uint32_t*)(wrow0 + kt*32 + 16);
            aW[kt][3] = *(const uint32_t*)(wrow8 + kt*32 + 16);
        }
    }
    float bia0 = bias[obase + g];
    float bia8 = bias[obase + 8 + g];
    float ob_g  = obias[g];
    float ob_g8 = obias[g + 8];

    int gh = lane >> 4;         // tap select in pair
    int c4 = lane & 15;         // channel group (4 channels)

    float sAcc = 0.f, qAcc = 0.f;  // per-thread BN partials

    for (int t = 0; t < 4; t++) {
        int tileIdx = blockIdx.x*4 + t;
        int pixbase = tileIdx*128;
        int b  = pixbase >> 16;
        int h  = (pixbase >> 8) & 255;
        int w0 = pixbase & 255;

        // ======== 1. stage S0 (unshifted rows) -> Shf fp16 ========
        #pragma unroll 2
        for (int it = 0; it < 24; it++) {
            int tap  = wid*48 + it*2 + gh;
            int kk   = tap >> 7;
            int pixg = tap & 127;
            float4 f = *((const float4*)(xt + ((b*HP + h + kk)*W_ + w0 + pixg)*C_) + c4);
            uint2 hv = make_uint2(h2u(f.x, f.y), h2u(f.z, f.w));
            *(uint2*)(Shf + pixg*WROW + kk*128 + c4*8) = hv;
        }
        __syncthreads();

        // ======== 2. om mma: warp handles 16 px (pxw..pxw+15) ========
        {
            int pxw = wid*16;
            float oc[2][4];
            #pragma unroll
            for (int ng = 0; ng < 2; ng++)
                #pragma unroll
                for (int j = 0; j < 4; j++) oc[ng][j] = 0.f;
            const char* w0p = smem + WOF_OFF + g*WROW     + tg*4;
            const char* w8p = smem + WOF_OFF + (8+g)*WROW + tg*4;
            #pragma unroll
            for (int kt = 0; kt < 12; kt++) {
                uint32_t a0 = *(const uint32_t*)(w0p + kt*32);
                uint32_t a1 = *(const uint32_t*)(w8p + kt*32);
                uint32_t a2 = *(const uint32_t*)(w0p + kt*32 + 16);
                uint32_t a3 = *(const uint32_t*)(w8p + kt*32 + 16);
                #pragma unroll
                for (int ng = 0; ng < 2; ng++) {
                    const char* sp = Shf + (pxw + ng*8 + g)*WROW + tg*4 + kt*32;
                    uint32_t b0 = *(const uint32_t*)(sp);
                    uint32_t b1 = *(const uint32_t*)(sp + 16);
                    mma16816(oc[ng][0], oc[ng][1], oc[ng][2], oc[ng][3],
                             a0, a1, a2, a3, b0, b1);
                }
            }
            // write om -> meta: row g (ch 0..7), row g+8 valid only for g==0 (ch 8)
            #pragma unroll
            for (int ng = 0; ng < 2; ng++) {
                int px = pxw + ng*8 + 2*tg;
                float v0 = oc[ng][0] + ob_g;
                float v1 = oc[ng][1] + ob_g;
                if (g >= 6) {
                    v0 = 1.f/(1.f + __expf(-v0));
                    v1 = 1.f/(1.f + __expf(-v1));
                }
                meta[g*132 + px]     = v0;
                meta[g*132 + px + 1] = v1;
                if (g == 0) {   // ch 8 = mask -> sigmoid
                    float v2 = oc[ng][2] + ob_g8;
                    float v3 = oc[ng][3] + ob_g8;
                    v2 = 1.f/(1.f + __expf(-v2));
                    v3 = 1.f/(1.f + __expf(-v3));
                    meta[8*132 + px]     = v2;
                    meta[8*132 + px + 1] = v3;
                }
            }
        }
        __syncthreads();

        // ======== 3. gather 384 taps -> Shf[px][k] fp16 ========
        #pragma unroll 2
        for (int it = 0; it < 24; it++) {
            int tap  = wid*48 + it*2 + gh;
            int kk   = tap >> 7;
            int pixg = tap & 127;
            int wxp  = w0 + pixg;
            float dy = meta[kk*132 + pixg];
            float dx = meta[(3+kk)*132 + pixg];
            float mv = meta[(6+kk)*132 + pixg];
            float y  = (float)(h + kk) + dy;
            float xf = (float)wxp + dx;
            float y0 = floorf(y), x0 = floorf(xf);
            float fy = y - y0, fx = xf - x0;
            int iy0 = (int)y0, ix0 = (int)x0;
            int iy1 = iy0 + 1, ix1 = ix0 + 1;
            bool vy0 = (iy0 >= 0) && (iy0 <= HP-1);
            bool vy1 = (iy1 >= 0) && (iy1 <= HP-1);
            bool vx0 = (ix0 >= 0) && (ix0 <= W_-1);
            bool vx1 = (ix1 >= 0) && (ix1 <= W_-1);
            float gy0 = 1.f - fy, gx0 = 1.f - fx;
            float q00 = gy0*gx0*mv; if (!(vy0 && vx0)) q00 = 0.f;
            float q01 = gy0*fx*mv;  if (!(vy0 && vx1)) q01 = 0.f;
            float q10 = fy*gx0*mv;  if (!(vy1 && vx0)) q10 = 0.f;
            float q11 = fy*fx*mv;   if (!(vy1 && vx1)) q11 = 0.f;
            int cy0 = min(max(iy0,0),HP-1), cy1 = min(max(iy1,0),HP-1);
            int cx0 = min(max(ix0,0),W_-1), cx1 = min(max(ix1,0),W_-1);
            int rb = b*HP;
            ulonglong2 u00 = *((const ulonglong2*)(xt + ((rb+cy0)*W_+cx0)*C_) + c4);
            ulonglong2 u01 = *((const ulonglong2*)(xt + ((rb+cy0)*W_+cx1)*C_) + c4);
            ulonglong2 u10 = *((const ulonglong2*)(xt + ((rb+cy1)*W_+cx0)*C_) + c4);
            ulonglong2 u11 = *((const ulonglong2*)(xt + ((rb+cy1)*W_+cx1)*C_) + c4);
            uint64_t a01 = 0ull, a23 = 0ull;
            uint64_t pp;
            pp = pack2(q00, q00); ffma2(a01, u00.x, pp); ffma2(a23, u00.y, pp);
            pp = pack2(q01, q01); ffma2(a01, u01.x, pp); ffma2(a23, u01.y, pp);
            pp = pack2(q10, q10); ffma2(a01, u10.x, pp); ffma2(a23, u10.y, pp);
            pp = pack2(q11, q11); ffma2(a01, u11.x, pp); ffma2(a23, u11.y, pp);
            float v0, v1, v2, v3;
            unpack2(v0, v1, a01);
            unpack2(v2, v3, a23);
            uint2 hv = make_uint2(h2u(v0, v1), h2u(v2, v3));
            *(uint2*)(Shf + pixg*WROW + kk*128 + c4*8) = hv;
        }
        __syncthreads();

        // ======== 4. main GEMM: 96 mma.sync per warp ========
        float acc[8][4];
        #pragma unroll
        for (int ng = 0; ng < 8; ng++)
            #pragma unroll
            for (int j = 0; j < 4; j++) acc[ng][j] = 0.f;

        {
            const char* sBase = Shf + (pxbase + g)*WROW + tg*4;
            #pragma unroll
            for (int kt = 0; kt < 12; kt++) {
                const char* sk = sBase + kt*32;
                #pragma unroll
                for (int ng = 0; ng < 8; ng++) {
                    uint32_t b0 = *(const uint32_t*)(sk + ng*(8*WROW));
                    uint32_t b1 = *(const uint32_t*)(sk + ng*(8*WROW) + 16);
                    mma16816(acc[ng][0], acc[ng][1], acc[ng][2], acc[ng][3],
                             aW[kt][0], aW[kt][1], aW[kt][2], aW[kt][3], b0, b1);
                }
            }
        }
        __syncthreads();   // all warps done reading Shf before osh overlays it

        // ======== epilogue: acc -> osh[o][px] (+bias) ========
        {
            float* o0 = osh + (obase + g)*132     + pxbase + 2*tg;
            float* o8 = osh + (obase + 8 + g)*132 + pxbase + 2*tg;
            #pragma unroll
            for (int ng = 0; ng < 8; ng++) {
                *(float2*)(o0 + ng*8) = make_float2(acc[ng][0] + bia0, acc[ng][1] + bia0);
                *(float2*)(o8 + ng*8) = make_float2(acc[ng][2] + bia8, acc[ng][3] + bia8);
            }
        }
        __syncthreads();

        // ======== BN partials for this tile ========
        {
            int o = tid >> 2, q4 = tid & 3;
            const float* r = osh + o*132 + q4*32;
            float s = 0.f, q = 0.f;
            #pragma unroll
            for (int j = 0; j < 32; j++) { float v = r[j]; s += v; q += v*v; }
            meta[tid] = s;            // meta reused as scratch; rebuilt next tile
            meta[256 + tid] = q;
        }
        __syncthreads();
        if (tid < 64) {
            sAcc += meta[tid*4] + meta[tid*4+1] + meta[tid*4+2] + meta[tid*4+3];
            qAcc += meta[256 + tid*4] + meta[256 + tid*4+1]
                  + meta[256 + tid*4+2] + meta[256 + tid*4+3];
        }

        // ======== coalesced NCHW store of 64 x 128 tile ========
        int obase2 = (b*C_*H_ + h)*W_ + w0;
        #pragma unroll
        for (int rep = 0; rep < 32; rep++) {
            int idx = rep*256 + tid;
            int o = idx >> 7, p = idx & 127;
            out[obase2 + o*H_*W_ + p] = osh[o*132 + p];
        }
        __syncthreads();
    }

    // ---- per-block BN partials ----
    if (tid < 64) {
        g_part[blockIdx.x*128 + tid]      = sAcc;
        g_part[blockIdx.x*128 + 64 + tid] = qAcc;
    }
}

// ------------------------------------------------------ BN stats -> affine A,B
__global__ void k_stats(const float* __restrict__ gamma,
                        const float* __restrict__ beta) {
    int o = blockIdx.x;
    int tid = threadIdx.x;
    __shared__ float rs[256], rq[256];
    float s = 0.f, q = 0.f;
    for (int j = tid; j < MAIN_BLOCKS; j += 256) {
        s += g_part[j*128 + o];
        q += g_part[j*128 + 64 + o];
    }
    rs[tid] = s; rq[tid] = q;
    __syncthreads();
    for (int st = 128; st > 0; st >>= 1) {
        if (tid < st) { rs[tid] += rs[tid+st]; rq[tid] += rq[tid+st]; }
        __syncthreads();
    }
    if (tid == 0) {
        float n = (float)NPIX;
        float mean = rs[0]/n;
        float var  = rq[0]/n - mean*mean;
        float inv  = rsqrtf(var + 1e-5f);
        float A = gamma[o]*inv;
        g_ab[o]      = A;
        g_ab[64 + o] = beta[o] - mean*A;
    }
}

// -------------------------------------------------------- normalize + ReLU
__global__ void k_norm(float* __restrict__ out) {
    int i = blockIdx.x*256 + threadIdx.x;
    int o = (i >> 14) & 63;
    float A = g_ab[o], Bv = g_ab[64 + o];
    float4 v = ((float4*)out)[i];
    v.x = fmaxf(fmaf(v.x, A, Bv), 0.f);
    v.y = fmaxf(fmaf(v.y, A, Bv), 0.f);
    v.z = fmaxf(fmaf(v.z, A, Bv), 0.f);
    v.w = fmaxf(fmaf(v.w, A, Bv), 0.f);
    ((float4*)out)[i] = v;
}

extern "C" void kernel_launch(void* const* d_in, const int* in_sizes, int n_in,
                              void* d_out, int out_size) {
    const float* x     = (const float*)d_in[0];
    const float* w_off = (const float*)d_in[1];
    const float* b_off = (const float*)d_in[2];
    const float* w_dcn = (const float*)d_in[3];
    const float* b_dcn = (const float*)d_in[4];
    const float* gamma = (const float*)d_in[5];
    const float* beta  = (const float*)d_in[6];
    float* out = (float*)d_out;

    cudaFuncSetAttribute(k_main, cudaFuncAttributeMaxDynamicSharedMemorySize, SMEM_BYTES);

    k_zero_pad<<<1024, 256>>>();
    k_transpose<<<dim3(8, 2, B_*H_), dim3(32, 8)>>>(x);
    k_main<<<MAIN_BLOCKS, 256, SMEM_BYTES>>>(w_dcn, b_dcn, w_off, b_off, out);
    k_stats<<<64, 256>>>(gamma, beta);
    k_norm<<<NPIX*C_/4/256, 256>>>(out);
}

// round 16
// speedup vs baseline: 2.1635x; 1.0359x over previous
#include <cuda_runtime.h>
#include <cuda_fp16.h>
#include <math.h>
#include <stdint.h>

#define B_ 8
#define C_ 64
#define H_ 256
#define W_ 256
#define HP 258
#define NPIX (B_*H_*W_)          // 524288
#define MAIN_BLOCKS 1024         // 4096 tiles of 128 pixels, 4 per block

// ---- smem layout (bytes). fp16 rows are 192 halves = 384 B; stride 400 B. ----
#define WROW 400
#define WHF_OFF   0                         // [64 o][400B]  fp16 weights
#define WHF_BYTES (64*WROW)                 // 25600
#define WOF_OFF   (WHF_OFF + WHF_BYTES)     // [16 oc][400B] fp16 offset-conv W
#define WOF_BYTES (16*WROW)                 // 6400
#define SHF_OFF   (WOF_OFF + WOF_BYTES)     // [128 px][400B] fp16 sampled
#define SHF_BYTES (128*WROW)                // 51200
#define META_OFF  (SHF_OFF + SHF_BYTES)     // [9][132] f32
#define META_BYTES (9*132*4)                // 4752
#define BIAS_OFF  (META_OFF + META_BYTES)   // 64 f32 (dcn bias) + 16 f32 (off bias)
#define SMEM_BYTES (BIAS_OFF + 384 + 256)
// osh [64 o][132] f32 (33792 B) overlays Shf after the main GEMM phase.

// ---- device scratch ----
__device__ __half g_xt[B_*HP*W_*C_];    // padded channel-last input, fp16 (68MB)
__device__ __half g_raw[NPIX*C_];       // pre-BN output, fp16 NCHW (67MB)
__device__ float g_part[MAIN_BLOCKS*128];
__device__ float g_ab[128];

// ---- helpers ----
__device__ __forceinline__ void mma16816(float& c0, float& c1, float& c2, float& c3,
                                         uint32_t a0, uint32_t a1, uint32_t a2, uint32_t a3,
                                         uint32_t b0, uint32_t b1) {
    asm volatile(
        "mma.sync.aligned.m16n8k16.row.col.f32.f16.f16.f32 "
        "{%0,%1,%2,%3}, {%4,%5,%6,%7}, {%8,%9}, {%0,%1,%2,%3};"
        : "+f"(c0), "+f"(c1), "+f"(c2), "+f"(c3)
        : "r"(a0), "r"(a1), "r"(a2), "r"(a3), "r"(b0), "r"(b1));
}
__device__ __forceinline__ uint32_t h2u(float lo, float hi) {
    __half2 h = __floats2half2_rn(lo, hi);
    return *(uint32_t*)&h;
}
__device__ __forceinline__ float2 u2f2(uint32_t u) {
    return __half22float2(*(__half2*)&u);
}

// ---------------------------------------------------------------- zero pad rows
__global__ void k_zero_pad() {
    int i = blockIdx.x*256 + threadIdx.x;      // 131072 uint32 words
    int b = i >> 14;
    int r = (i >> 13) & 1;
    int j = i & 8191;                           // word within row (W*C/2)
    ((uint32_t*)g_xt)[(b*HP + r*257)*(W_*C_/2) + j] = 0u;
}

// ------------------------------------------------- NCHW fp32 -> padded CL fp16
__global__ void k_transpose(const float* __restrict__ x) {
    __shared__ float tile[32][33];
    int wb = blockIdx.x*32, cb = blockIdx.y*32;
    int b = blockIdx.z >> 8, h = blockIdx.z & 255;
    int tx = threadIdx.x, ty = threadIdx.y;
    #pragma unroll
    for (int i = 0; i < 4; i++) {
        int c = cb + ty + 8*i;
        tile[ty+8*i][tx] = x[((b*C_ + c)*H_ + h)*W_ + wb + tx];
    }
    __syncthreads();
    #pragma unroll
    for (int i = 0; i < 4; i++) {
        int w = wb + ty + 8*i;
        g_xt[((b*HP + h + 1)*W_ + w)*C_ + cb + tx] = __float2half_rn(tile[tx][ty+8*i]);
    }
}

// ------------------------------------------------------------- main DCN kernel
// Per 128-pixel tile:
//  1. stage S0[px][192] = xt rows h-1..h+1 (fp16 copy) into Shf
//  2. om[9][128] = Wof x S0^T via mma -> meta (+bias, sigmoid)
//  3. gather with bilinear offsets (fp16 loads, fp32 blend) -> Shf
//  4. out[64 o][128 px] = Wdcn x Shf^T via mma -> g_raw (fp16) + BN partials
__global__ void __launch_bounds__(256, 2)
k_main(const float* __restrict__ w_dcn,
       const float* __restrict__ b_dcn,
       const float* __restrict__ w_off,
       const float* __restrict__ b_off) {
    extern __shared__ char smem[];
    char*   Shf  = smem + SHF_OFF;
    float*  meta = (float*)(smem + META_OFF);
    float*  bias = (float*)(smem + BIAS_OFF);        // [64] dcn bias
    float*  obias = (float*)(smem + BIAS_OFF + 256); // [16] offset-conv bias
    float*  osh  = (float*)(smem + SHF_OFF);         // overlay, valid post-GEMM

    const __half* __restrict__ xt = g_xt;

    int tid = threadIdx.x;
    int lane = tid & 31, wid = tid >> 5;
    int g  = lane >> 2;         // mma group id (0-7)
    int tg = lane & 3;          // thread-in-group

    // ---- fill Whf[o][k] fp16 (row stride 400 B)
    for (int i = tid; i < 64*192; i += 256) {
        int o = i / 192, k = i - o*192;
        int c = k & 63, kk = k >> 6;
        *(__half*)(smem + WHF_OFF + o*WROW + k*2) =
            __float2half_rn(w_dcn[(o*C_ + c)*3 + kk]);
    }
    // ---- fill Wof[oc][k] fp16, rows 9..15 zero
    for (int i = tid; i < 16*192; i += 256) {
        int o = i / 192, k = i - o*192;
        int c = k & 63, kk = k >> 6;
        float v = (o < 9) ? w_off[(o*C_ + c)*3 + kk] : 0.f;
        *(__half*)(smem + WOF_OFF + o*WROW + k*2) = __float2half_rn(v);
    }
    if (tid < 64) bias[tid] = b_dcn[tid];
    if (tid >= 64 && tid < 80) obias[tid-64] = (tid-64 < 9) ? b_off[tid-64] : 0.f;
    __syncthreads();

    // ---- warp tile coords (main GEMM)
    int obase  = (wid & 3) * 16;
    int pxbase = (wid >> 2) * 64;

    // ---- preload W fragments: aW[kt][0..3]
    uint32_t aW[12][4];
    {
        const char* wrow0 = smem + WHF_OFF + (obase + g)*WROW     + tg*4;
        const char* wrow8 = smem + WHF_OFF + (obase + 8 + g)*WROW + tg*4;
        #pragma unroll
        for (int kt = 0; kt < 12; kt++) {
            aW[kt][0] = *(const uint32_t*)(wrow0 + kt*32);
            aW[kt][1] = *(const uint32_t*)(wrow8 + kt*32);
            aW[kt][2] = *(const uint32_t*)(wrow0 + kt*32 + 16);
            aW[kt][3] = *(const uint32_t*)(wrow8 + kt*32 + 16);
        }
    }
    float bia0 = bias[obase + g];
    float bia8 = bias[obase + 8 + g];
    float ob_g  = obias[g];
    float ob_g8 = obias[g + 8];

    int gh = lane >> 4;         // tap select in pair
    int c4 = lane & 15;         // channel group (4 channels)

    float sAcc = 0.f, qAcc = 0.f;  // per-thread BN partials

    for (int t = 0; t < 4; t++) {
        int tileIdx = blockIdx.x*4 + t;
        int pixbase = tileIdx*128;
        int b  = pixbase >> 16;
        int h  = (pixbase >> 8) & 255;
        int w0 = pixbase & 255;

        // ======== 1. stage S0 (unshifted rows) -> Shf, pure fp16 copy ========
        #pragma unroll 2
        for (int it = 0; it < 24; it++) {
            int tap  = wid*48 + it*2 + gh;
            int kk   = tap >> 7;
            int pixg = tap & 127;
            uint2 u = *((const uint2*)(xt + ((b*HP + h + kk)*W_ + w0 + pixg)*C_) + c4);
            *(uint2*)(Shf + pixg*WROW + kk*128 + c4*8) = u;
        }
        __syncthreads();

        // ======== 2. om mma: warp handles 16 px (pxw..pxw+15) ========
        {
            int pxw = wid*16;
            float oc[2][4];
            #pragma unroll
            for (int ng = 0; ng < 2; ng++)
                #pragma unroll
                for (int j = 0; j < 4; j++) oc[ng][j] = 0.f;
            const char* w0p = smem + WOF_OFF + g*WROW     + tg*4;
            const char* w8p = smem + WOF_OFF + (8+g)*WROW + tg*4;
            #pragma unroll
            for (int kt = 0; kt < 12; kt++) {
                uint32_t a0 = *(const uint32_t*)(w0p + kt*32);
                uint32_t a1 = *(const uint32_t*)(w8p + kt*32);
                uint32_t a2 = *(const uint32_t*)(w0p + kt*32 + 16);
                uint32_t a3 = *(const uint32_t*)(w8p + kt*32 + 16);
                #pragma unroll
                for (int ng = 0; ng < 2; ng++) {
                    const char* sp = Shf + (pxw + ng*8 + g)*WROW + tg*4 + kt*32;
                    uint32_t b0 = *(const uint32_t*)(sp);
                    uint32_t b1 = *(const uint32_t*)(sp + 16);
                    mma16816(oc[ng][0], oc[ng][1], oc[ng][2], oc[ng][3],
                             a0, a1, a2, a3, b0, b1);
                }
            }
            #pragma unroll
            for (int ng = 0; ng < 2; ng++) {
                int px = pxw + ng*8 + 2*tg;
                float v0 = oc[ng][0] + ob_g;
                float v1 = oc[ng][1] + ob_g;
                if (g >= 6) {
                    v0 = 1.f/(1.f + __expf(-v0));
                    v1 = 1.f/(1.f + __expf(-v1));
                }
                meta[g*132 + px]     = v0;
                meta[g*132 + px + 1] = v1;
                if (g == 0) {   // ch 8 = mask -> sigmoid
                    float v2 = oc[ng][2] + ob_g8;
                    float v3 = oc[ng][3] + ob_g8;
                    v2 = 1.f/(1.f + __expf(-v2));
                    v3 = 1.f/(1.f + __expf(-v3));
                    meta[8*132 + px]     = v2;
                    meta[8*132 + px + 1] = v3;
                }
            }
        }
        __syncthreads();

        // ======== 3. gather 384 taps -> Shf[px][k] fp16 ========
        #pragma unroll 2
        for (int it = 0; it < 24; it++) {
            int tap  = wid*48 + it*2 + gh;
            int kk   = tap >> 7;
            int pixg = tap & 127;
            int wxp  = w0 + pixg;
            float dy = meta[kk*132 + pixg];
            float dx = meta[(3+kk)*132 + pixg];
            float mv = meta[(6+kk)*132 + pixg];
            float y  = (float)(h + kk) + dy;
            float xf = (float)wxp + dx;
            float y0 = floorf(y), x0 = floorf(xf);
            float fy = y - y0, fx = xf - x0;
            int iy0 = (int)y0, ix0 = (int)x0;
            int iy1 = iy0 + 1, ix1 = ix0 + 1;
            bool vy0 = (iy0 >= 0) && (iy0 <= HP-1);
            bool vy1 = (iy1 >= 0) && (iy1 <= HP-1);
            bool vx0 = (ix0 >= 0) && (ix0 <= W_-1);
            bool vx1 = (ix1 >= 0) && (ix1 <= W_-1);
            float gy0 = 1.f - fy, gx0 = 1.f - fx;
            float q00 = gy0*gx0*mv; if (!(vy0 && vx0)) q00 = 0.f;
            float q01 = gy0*fx*mv;  if (!(vy0 && vx1)) q01 = 0.f;
            float q10 = fy*gx0*mv;  if (!(vy1 && vx0)) q10 = 0.f;
            float q11 = fy*fx*mv;   if (!(vy1 && vx1)) q11 = 0.f;
            int cy0 = min(max(iy0,0),HP-1), cy1 = min(max(iy1,0),HP-1);
            int cx0 = min(max(ix0,0),W_-1), cx1 = min(max(ix1,0),W_-1);
            int rb = b*HP;
            uint2 u00 = *((const uint2*)(xt + ((rb+cy0)*W_+cx0)*C_) + c4);
            uint2 u01 = *((const uint2*)(xt + ((rb+cy0)*W_+cx1)*C_) + c4);
            uint2 u10 = *((const uint2*)(xt + ((rb+cy1)*W_+cx0)*C_) + c4);
            uint2 u11 = *((const uint2*)(xt + ((rb+cy1)*W_+cx1)*C_) + c4);
            float2 fa, fb;
            float v0, v1, v2, v3;
            fa = u2f2(u00.x); fb = u2f2(u00.y);
            v0 = q00*fa.x; v1 = q00*fa.y; v2 = q00*fb.x; v3 = q00*fb.y;
            fa = u2f2(u01.x); fb = u2f2(u01.y);
            v0 = fmaf(q01, fa.x, v0); v1 = fmaf(q01, fa.y, v1);
            v2 = fmaf(q01, fb.x, v2); v3 = fmaf(q01, fb.y, v3);
            fa = u2f2(u10.x); fb = u2f2(u10.y);
            v0 = fmaf(q10, fa.x, v0); v1 = fmaf(q10, fa.y, v1);
            v2 = fmaf(q10, fb.x, v2); v3 = fmaf(q10, fb.y, v3);
            fa = u2f2(u11.x); fb = u2f2(u11.y);
            v0 = fmaf(q11, fa.x, v0); v1 = fmaf(q11, fa.y, v1);
            v2 = fmaf(q11, fb.x, v2); v3 = fmaf(q11, fb.y, v3);
            uint2 hv = make_uint2(h2u(v0, v1), h2u(v2, v3));
            *(uint2*)(Shf + pixg*WROW + kk*128 + c4*8) = hv;
        }
        __syncthreads();

        // ======== 4. main GEMM: 96 mma.sync per warp ========
        float acc[8][4];
        #pragma unroll
        for (int ng = 0; ng < 8; ng++)
            #pragma unroll
            for (int j = 0; j < 4; j++) acc[ng][j] = 0.f;

        {
            const char* sBase = Shf + (pxbase + g)*WROW + tg*4;
            #pragma unroll
            for (int kt = 0; kt < 12; kt++) {
                const char* sk = sBase + kt*32;
                #pragma unroll
                for (int ng = 0; ng < 8; ng++) {
                    uint32_t b0 = *(const uint32_t*)(sk + ng*(8*WROW));
                    uint32_t b1 = *(const uint32_t*)(sk + ng*(8*WROW) + 16);
                    mma16816(acc[ng][0], acc[ng][1], acc[ng][2], acc[ng][3],
                             aW[kt][0], aW[kt][1], aW[kt][2], aW[kt][3], b0, b1);
                }
            }
        }
        __syncthreads();   // all warps done reading Shf before osh overlays it

        // ======== epilogue: acc -> osh[o][px] (+bias) ========
        {
            float* o0 = osh + (obase + g)*132     + pxbase + 2*tg;
            float* o8 = osh + (obase + 8 + g)*132 + pxbase + 2*tg;
            #pragma unroll
            for (int ng = 0; ng < 8; ng++) {
                *(float2*)(o0 + ng*8) = make_float2(acc[ng][0] + bia0, acc[ng][1] + bia0);
                *(float2*)(o8 + ng*8) = make_float2(acc[ng][2] + bia8, acc[ng][3] + bia8);
            }
        }
        __syncthreads();

        // ======== BN partials for this tile (fp32, pre-rounding) ========
        {
            int o = tid >> 2, q4 = tid & 3;
            const float* r = osh + o*132 + q4*32;
            float s = 0.f, q = 0.f;
            #pragma unroll
            for (int j = 0; j < 32; j++) { float v = r[j]; s += v; q += v*v; }
            meta[tid] = s;            // meta reused as scratch; rebuilt next tile
            meta[256 + tid] = q;
        }
        __syncthreads();
        if (tid < 64) {
            sAcc += meta[tid*4] + meta[tid*4+1] + meta[tid*4+2] + meta[tid*4+3];
            qAcc += meta[256 + tid*4] + meta[256 + tid*4+1]
                  + meta[256 + tid*4+2] + meta[256 + tid*4+3];
        }

        // ======== coalesced NCHW fp16 store of 64 x 128 tile ========
        int obase2 = (b*C_*H_ + h)*W_ + w0;
        #pragma unroll
        for (int rep = 0; rep < 16; rep++) {
            int idx = rep*256 + tid;
            int o = idx >> 6, pw = (idx & 63)*2;
            __half2 hv = __floats2half2_rn(osh[o*132 + pw], osh[o*132 + pw + 1]);
            *(__half2*)(g_raw + obase2 + o*H_*W_ + pw) = hv;
        }
        __syncthreads();
    }

    // ---- per-block BN partials ----
    if (tid < 64) {
        g_part[blockIdx.x*128 + tid]      = sAcc;
        g_part[blockIdx.x*128 + 64 + tid] = qAcc;
    }
}

// ------------------------------------------------------ BN stats -> affine A,B
__global__ void k_stats(const float* __restrict__ gamma,
                        const float* __restrict__ beta) {
    int o = blockIdx.x;
    int tid = threadIdx.x;
    __shared__ float rs[256], rq[256];
    float s = 0.f, q = 0.f;
    for (int j = tid; j < MAIN_BLOCKS; j += 256) {
        s += g_part[j*128 + o];
        q += g_part[j*128 + 64 + o];
    }
    rs[tid] = s; rq[tid] = q;
    __syncthreads();
    for (int st = 128; st > 0; st >>= 1) {
        if (tid < st) { rs[tid] += rs[tid+st]; rq[tid] += rq[tid+st]; }
        __syncthreads();
    }
    if (tid == 0) {
        float n = (float)NPIX;
        float mean = rs[0]/n;
        float var  = rq[0]/n - mean*mean;
        float inv  = rsqrtf(var + 1e-5f);
        float A = gamma[o]*inv;
        g_ab[o]      = A;
        g_ab[64 + o] = beta[o] - mean*A;
    }
}

// -------------------------------------------------------- normalize + ReLU
__global__ void k_norm(float* __restrict__ out) {
    int i = blockIdx.x*256 + threadIdx.x;     // 4 elements per thread
    int o = (i >> 14) & 63;
    float A = g_ab[o], Bv = g_ab[64 + o];
    uint2 u = ((const uint2*)g_raw)[i];
    float2 fa = u2f2(u.x), fb = u2f2(u.y);
    float4 v;
    v.x = fmaxf(fmaf(fa.x, A, Bv), 0.f);
    v.y = fmaxf(fmaf(fa.y, A, Bv), 0.f);
    v.z = fmaxf(fmaf(fb.x, A, Bv), 0.f);
    v.w = fmaxf(fmaf(fb.y, A, Bv), 0.f);
    ((float4*)out)[i] = v;
}

extern "C" void kernel_launch(void* const* d_in, const int* in_sizes, int n_in,
                              void* d_out, int out_size) {
    const float* x     = (const float*)d_in[0];
    const float* w_off = (const float*)d_in[1];
    const float* b_off = (const float*)d_in[2];
    const float* w_dcn = (const float*)d_in[3];
    const float* b_dcn = (const float*)d_in[4];
    const float* gamma = (const float*)d_in[5];
    const float* beta  = (const float*)d_in[6];
    float* out = (float*)d_out;

    cudaFuncSetAttribute(k_main, cudaFuncAttributeMaxDynamicSharedMemorySize, SMEM_BYTES);

    k_zero_pad<<<512, 256>>>();
    k_transpose<<<dim3(8, 2, B_*H_), dim3(32, 8)>>>(x);
    k_main<<<MAIN_BLOCKS, 256, SMEM_BYTES>>>(w_dcn, b_dcn, w_off, b_off);
    k_stats<<<64, 256>>>(gamma, beta);
    k_norm<<<NPIX*C_/4/256, 256>>>(out);
}

// round 17
// speedup vs baseline: 2.4755x; 1.1442x over previous
#include <cuda_runtime.h>
#include <cuda_fp16.h>
#include <math.h>
#include <stdint.h>

#define B_ 8
#define C_ 64
#define H_ 256
#define W_ 256
#define HP 258
#define NPIX (B_*H_*W_)          // 524288
#define MAIN_BLOCKS 1024         // 4096 tiles of 128 pixels, 4 per block

// ---- smem layout (bytes). fp16 rows are 192 halves = 384 B; stride 400 B. ----
#define WROW 400
#define WOF_OFF   0                         // [16 oc][400B] fp16 offset-conv W
#define WOF_BYTES (16*WROW)                 // 6400
#define SHF_OFF   (WOF_OFF + WOF_BYTES)     // [128 px][400B] fp16 sampled
#define SHF_BYTES (128*WROW)                // 51200
#define META_OFF  (SHF_OFF + SHF_BYTES)     // [9][132] f32
#define META_BYTES (9*132*4)                // 4752
#define BIAS_OFF  (META_OFF + META_BYTES)   // 64 f32 (dcn bias) + 16 f32 (off bias)
#define SMEM_BYTES (BIAS_OFF + 384 + 64)    // ~62.8 KB -> 3 CTAs/SM
// osh [64 o][132] f32 (33792 B) overlays Shf after the main GEMM phase.

// ---- device scratch ----
__device__ __half g_xt[B_*HP*W_*C_];    // padded channel-last input, fp16 (68MB)
__device__ __half g_raw[NPIX*C_];       // pre-BN output, fp16 NCHW (67MB)
__device__ uint4  g_wfrag[4*12*32];     // packed mma A-fragments, 24.6KB, L1-hot
__device__ float g_part[MAIN_BLOCKS*128];
__device__ float g_ab[128];

// ---- helpers ----
__device__ __forceinline__ void mma16816(float& c0, float& c1, float& c2, float& c3,
                                         uint32_t a0, uint32_t a1, uint32_t a2, uint32_t a3,
                                         uint32_t b0, uint32_t b1) {
    asm volatile(
        "mma.sync.aligned.m16n8k16.row.col.f32.f16.f16.f32 "
        "{%0,%1,%2,%3}, {%4,%5,%6,%7}, {%8,%9}, {%0,%1,%2,%3};"
        : "+f"(c0), "+f"(c1), "+f"(c2), "+f"(c3)
        : "r"(a0), "r"(a1), "r"(a2), "r"(a3), "r"(b0), "r"(b1));
}
__device__ __forceinline__ uint32_t h2u(float lo, float hi) {
    __half2 h = __floats2half2_rn(lo, hi);
    return *(uint32_t*)&h;
}
__device__ __forceinline__ float2 u2f2(uint32_t u) {
    return __half22float2(*(__half2*)&u);
}

// ---------------------------------------------------------------- zero pad rows
__global__ void k_zero_pad() {
    int i = blockIdx.x*256 + threadIdx.x;      // 131072 uint32 words
    int b = i >> 14;
    int r = (i >> 13) & 1;
    int j = i & 8191;                           // word within row (W*C/2)
    ((uint32_t*)g_xt)[(b*HP + r*257)*(W_*C_/2) + j] = 0u;
}

// ----------------------------------------- pack mma A-fragments for main GEMM
// g_wfrag[w4][kt][lane] = uint4 {a0,a1,a2,a3}; thread (wid&3=w4, lane) at k-step
// kt loads this as one LDG.128. a_j covers k-pair idx = tg + kt*8 + (j>>1)*4 of
// output row (w4*16 + g) for even j / (+8) for odd j.
__global__ void k_winit(const float* __restrict__ w_dcn) {
    int idx = blockIdx.x*256 + threadIdx.x;    // 1536 entries
    if (idx >= 4*12*32) return;
    int w4   = idx / 384;
    int r    = idx - w4*384;
    int kt   = r >> 5;
    int lane = r & 31;
    int g  = lane >> 2, tg = lane & 3;
    uint32_t a[4];
    #pragma unroll
    for (int j = 0; j < 4; j++) {
        int o = w4*16 + g + ((j & 1) ? 8 : 0);
        int ik = tg + kt*8 + ((j >> 1) ? 4 : 0);
        int k0 = 2*ik, k1 = k0 + 1;
        float f0 = w_dcn[(o*C_ + (k0 & 63))*3 + (k0 >> 6)];
        float f1 = w_dcn[(o*C_ + (k1 & 63))*3 + (k1 >> 6)];
        a[j] = h2u(f0, f1);
    }
    g_wfrag[idx] = make_uint4(a[0], a[1], a[2], a[3]);
}

// ------------------------------------------------- NCHW fp32 -> padded CL fp16
__global__ void k_transpose(const float* __restrict__ x) {
    __shared__ float tile[32][33];
    int wb = blockIdx.x*32, cb = blockIdx.y*32;
    int b = blockIdx.z >> 8, h = blockIdx.z & 255;
    int tx = threadIdx.x, ty = threadIdx.y;
    #pragma unroll
    for (int i = 0; i < 4; i++) {
        int c = cb + ty + 8*i;
        tile[ty+8*i][tx] = x[((b*C_ + c)*H_ + h)*W_ + wb + tx];
    }
    __syncthreads();
    #pragma unroll
    for (int i = 0; i < 4; i++) {
        int w = wb + ty + 8*i;
        g_xt[((b*HP + h + 1)*W_ + w)*C_ + cb + tx] = __float2half_rn(tile[tx][ty+8*i]);
    }
}

// ------------------------------------------------------------- main DCN kernel
// Per 128-pixel tile:
//  1. stage S0[px][192] = xt rows h-1..h+1 (fp16 copy) into Shf
//  2. om[9][128] = Wof x S0^T via mma -> meta (+bias, sigmoid)
//  3. gather with bilinear offsets (fp16 loads, fp32 blend) -> Shf
//  4. out[64 o][128 px] = Wdcn x Shf^T via mma -> g_raw (fp16) + BN partials
__global__ void __launch_bounds__(256, 3)
k_main(const float* __restrict__ b_dcn,
       const float* __restrict__ w_off,
       const float* __restrict__ b_off) {
    extern __shared__ char smem[];
    char*   Shf  = smem + SHF_OFF;
    float*  meta = (float*)(smem + META_OFF);
    float*  bias = (float*)(smem + BIAS_OFF);        // [64] dcn bias
    float*  obias = (float*)(smem + BIAS_OFF + 256); // [16] offset-conv bias
    float*  osh  = (float*)(smem + SHF_OFF);         // overlay, valid post-GEMM

    const __half* __restrict__ xt = g_xt;

    int tid = threadIdx.x;
    int lane = tid & 31, wid = tid >> 5;
    int g  = lane >> 2;         // mma group id (0-7)
    int tg = lane & 3;          // thread-in-group

    // ---- fill Wof[oc][k] fp16, rows 9..15 zero
    for (int i = tid; i < 16*192; i += 256) {
        int o = i / 192, k = i - o*192;
        int c = k & 63, kk = k >> 6;
        float v = (o < 9) ? w_off[(o*C_ + c)*3 + kk] : 0.f;
        *(__half*)(smem + WOF_OFF + o*WROW + k*2) = __float2half_rn(v);
    }
    if (tid < 64) bias[tid] = b_dcn[tid];
    if (tid >= 64 && tid < 80) obias[tid-64] = (tid-64 < 9) ? b_off[tid-64] : 0.f;
    __syncthreads();

    // ---- warp tile coords (main GEMM)
    int obase  = (wid & 3) * 16;
    int pxbase = (wid >> 2) * 64;
    const uint4* wfrag = g_wfrag + (wid & 3)*384 + lane;

    float bia0 = bias[obase + g];
    float bia8 = bias[obase + 8 + g];
    float ob_g  = obias[g];
    float ob_g8 = obias[g + 8];

    int gh = lane >> 4;         // tap select in pair
    int c4 = lane & 15;         // channel group (4 channels)

    float sAcc = 0.f, qAcc = 0.f;  // per-thread BN partials

    for (int t = 0; t < 4; t++) {
        int tileIdx = blockIdx.x*4 + t;
        int pixbase = tileIdx*128;
        int b  = pixbase >> 16;
        int h  = (pixbase >> 8) & 255;
        int w0 = pixbase & 255;

        // ======== 1. stage S0 (unshifted rows) -> Shf, pure fp16 copy ========
        #pragma unroll 2
        for (int it = 0; it < 24; it++) {
            int tap  = wid*48 + it*2 + gh;
            int kk   = tap >> 7;
            int pixg = tap & 127;
            uint2 u = *((const uint2*)(xt + ((b*HP + h + kk)*W_ + w0 + pixg)*C_) + c4);
            *(uint2*)(Shf + pixg*WROW + kk*128 + c4*8) = u;
        }
        __syncthreads();

        // ======== 2. om mma: warp handles 16 px (pxw..pxw+15) ========
        {
            int pxw = wid*16;
            float oc[2][4];
            #pragma unroll
            for (int ng = 0; ng < 2; ng++)
                #pragma unroll
                for (int j = 0; j < 4; j++) oc[ng][j] = 0.f;
            const char* w0p = smem + WOF_OFF + g*WROW     + tg*4;
            const char* w8p = smem + WOF_OFF + (8+g)*WROW + tg*4;
            #pragma unroll
            for (int kt = 0; kt < 12; kt++) {
                uint32_t a0 = *(const uint32_t*)(w0p + kt*32);
                uint32_t a1 = *(const uint32_t*)(w8p + kt*32);
                uint32_t a2 = *(const uint32_t*)(w0p + kt*32 + 16);
                uint32_t a3 = *(const uint32_t*)(w8p + kt*32 + 16);
                #pragma unroll
                for (int ng = 0; ng < 2; ng++) {
                    const char* sp = Shf + (pxw + ng*8 + g)*WROW + tg*4 + kt*32;
                    uint32_t b0 = *(const uint32_t*)(sp);
                    uint32_t b1 = *(const uint32_t*)(sp + 16);
                    mma16816(oc[ng][0], oc[ng][1], oc[ng][2], oc[ng][3],
                             a0, a1, a2, a3, b0, b1);
                }
            }
            #pragma unroll
            for (int ng = 0; ng < 2; ng++) {
                int px = pxw + ng*8 + 2*tg;
                float v0 = oc[ng][0] + ob_g;
                float v1 = oc[ng][1] + ob_g;
                if (g >= 6) {
                    v0 = 1.f/(1.f + __expf(-v0));
                    v1 = 1.f/(1.f + __expf(-v1));
                }
                meta[g*132 + px]     = v0;
                meta[g*132 + px + 1] = v1;
                if (g == 0) {   // ch 8 = mask -> sigmoid
                    float v2 = oc[ng][2] + ob_g8;
                    float v3 = oc[ng][3] + ob_g8;
                    v2 = 1.f/(1.f + __expf(-v2));
                    v3 = 1.f/(1.f + __expf(-v3));
                    meta[8*132 + px]     = v2;
                    meta[8*132 + px + 1] = v3;
                }
            }
        }
        __syncthreads();

        // ======== 3. gather 384 taps -> Shf[px][k] fp16 ========
        #pragma unroll 2
        for (int it = 0; it < 24; it++) {
            int tap  = wid*48 + it*2 + gh;
            int kk   = tap >> 7;
            int pixg = tap & 127;
            int wxp  = w0 + pixg;
            float dy = meta[kk*132 + pixg];
            float dx = meta[(3+kk)*132 + pixg];
            float mv = meta[(6+kk)*132 + pixg];
            float y  = (float)(h + kk) + dy;
            float xf = (float)wxp + dx;
            float y0 = floorf(y), x0 = floorf(xf);
            float fy = y - y0, fx = xf - x0;
            int iy0 = (int)y0, ix0 = (int)x0;
            int iy1 = iy0 + 1, ix1 = ix0 + 1;
            bool vy0 = (iy0 >= 0) && (iy0 <= HP-1);
            bool vy1 = (iy1 >= 0) && (iy1 <= HP-1);
            bool vx0 = (ix0 >= 0) && (ix0 <= W_-1);
            bool vx1 = (ix1 >= 0) && (ix1 <= W_-1);
            float gy0 = 1.f - fy, gx0 = 1.f - fx;
            float q00 = gy0*gx0*mv; if (!(vy0 && vx0)) q00 = 0.f;
            float q01 = gy0*fx*mv;  if (!(vy0 && vx1)) q01 = 0.f;
            float q10 = fy*gx0*mv;  if (!(vy1 && vx0)) q10 = 0.f;
            float q11 = fy*fx*mv;   if (!(vy1 && vx1)) q11 = 0.f;
            int cy0 = min(max(iy0,0),HP-1), cy1 = min(max(iy1,0),HP-1);
            int cx0 = min(max(ix0,0),W_-1), cx1 = min(max(ix1,0),W_-1);
            int rb = b*HP;
            uint2 u00 = *((const uint2*)(xt + ((rb+cy0)*W_+cx0)*C_) + c4);
            uint2 u01 = *((const uint2*)(xt + ((rb+cy0)*W_+cx1)*C_) + c4);
            uint2 u10 = *((const uint2*)(xt + ((rb+cy1)*W_+cx0)*C_) + c4);
            uint2 u11 = *((const uint2*)(xt + ((rb+cy1)*W_+cx1)*C_) + c4);
            float2 fa, fb;
            float v0, v1, v2, v3;
            fa = u2f2(u00.x); fb = u2f2(u00.y);
            v0 = q00*fa.x; v1 = q00*fa.y; v2 = q00*fb.x; v3 = q00*fb.y;
            fa = u2f2(u01.x); fb = u2f2(u01.y);
            v0 = fmaf(q01, fa.x, v0); v1 = fmaf(q01, fa.y, v1);
            v2 = fmaf(q01, fb.x, v2); v3 = fmaf(q01, fb.y, v3);
            fa = u2f2(u10.x); fb = u2f2(u10.y);
            v0 = fmaf(q10, fa.x, v0); v1 = fmaf(q10, fa.y, v1);
            v2 = fmaf(q10, fb.x, v2); v3 = fmaf(q10, fb.y, v3);
            fa = u2f2(u11.x); fb = u2f2(u11.y);
            v0 = fmaf(q11, fa.x, v0); v1 = fmaf(q11, fa.y, v1);
            v2 = fmaf(q11, fb.x, v2); v3 = fmaf(q11, fb.y, v3);
            uint2 hv = make_uint2(h2u(v0, v1), h2u(v2, v3));
            *(uint2*)(Shf + pixg*WROW + kk*128 + c4*8) = hv;
        }
        __syncthreads();

        // ======== 4. main GEMM: 96 mma.sync per warp, A-frags from L1 ========
        float acc[8][4];
        #pragma unroll
        for (int ng = 0; ng < 8; ng++)
            #pragma unroll
            for (int j = 0; j < 4; j++) acc[ng][j] = 0.f;

        {
            const char* sBase = Shf + (pxbase + g)*WROW + tg*4;
            #pragma unroll
            for (int kt = 0; kt < 12; kt++) {
                uint4 a = wfrag[kt*32];
                const char* sk = sBase + kt*32;
                #pragma unroll
                for (int ng = 0; ng < 8; ng++) {
                    uint32_t b0 = *(const uint32_t*)(sk + ng*(8*WROW));
                    uint32_t b1 = *(const uint32_t*)(sk + ng*(8*WROW) + 16);
                    mma16816(acc[ng][0], acc[ng][1], acc[ng][2], acc[ng][3],
                             a.x, a.y, a.z, a.w, b0, b1);
                }
            }
        }
        __syncthreads();   // all warps done reading Shf before osh overlays it

        // ======== epilogue: acc -> osh[o][px] (+bias) ========
        {
            float* o0 = osh + (obase + g)*132     + pxbase + 2*tg;
            float* o8 = osh + (obase + 8 + g)*132 + pxbase + 2*tg;
            #pragma unroll
            for (int ng = 0; ng < 8; ng++) {
                *(float2*)(o0 + ng*8) = make_float2(acc[ng][0] + bia0, acc[ng][1] + bia0);
                *(float2*)(o8 + ng*8) = make_float2(acc[ng][2] + bia8, acc[ng][3] + bia8);
            }
        }
        __syncthreads();

        // ======== BN partials for this tile (fp32, pre-rounding) ========
        {
            int o = tid >> 2, q4 = tid & 3;
            const float* r = osh + o*132 + q4*32;
            float s = 0.f, q = 0.f;
            #pragma unroll
            for (int j = 0; j < 32; j++) { float v = r[j]; s += v; q += v*v; }
            meta[tid] = s;            // meta reused as scratch; rebuilt next tile
            meta[256 + tid] = q;
        }
        __syncthreads();
        if (tid < 64) {
            sAcc += meta[tid*4] + meta[tid*4+1] + meta[tid*4+2] + meta[tid*4+3];
            qAcc += meta[256 + tid*4] + meta[256 + tid*4+1]
                  + meta[256 + tid*4+2] + meta[256 + tid*4+3];
        }

        // ======== coalesced NCHW fp16 store of 64 x 128 tile ========
        int obase2 = (b*C_*H_ + h)*W_ + w0;
        #pragma unroll
        for (int rep = 0; rep < 16; rep++) {
            int idx = rep*256 + tid;
            int o = idx >> 6, pw = (idx & 63)*2;
            __half2 hv = __floats2half2_rn(osh[o*132 + pw], osh[o*132 + pw + 1]);
            *(__half2*)(g_raw + obase2 + o*H_*W_ + pw) = hv;
        }
        __syncthreads();
    }

    // ---- per-block BN partials ----
    if (tid < 64) {
        g_part[blockIdx.x*128 + tid]      = sAcc;
        g_part[blockIdx.x*128 + 64 + tid] = qAcc;
    }
}

// ------------------------------------------------------ BN stats -> affine A,B
__global__ void k_stats(const float* __restrict__ gamma,
                        const float* __restrict__ beta) {
    int o = blockIdx.x;
    int tid = threadIdx.x;
    __shared__ float rs[256], rq[256];
    float s = 0.f, q = 0.f;
    for (int j = tid; j < MAIN_BLOCKS; j += 256) {
        s += g_part[j*128 + o];
        q += g_part[j*128 + 64 + o];
    }
    rs[tid] = s; rq[tid] = q;
    __syncthreads();
    for (int st = 128; st > 0; st >>= 1) {
        if (tid < st) { rs[tid] += rs[tid+st]; rq[tid] += rq[tid+st]; }
        __syncthreads();
    }
    if (tid == 0) {
        float n = (float)NPIX;
        float mean = rs[0]/n;
        float var  = rq[0]/n - mean*mean;
        float inv  = rsqrtf(var + 1e-5f);
        float A = gamma[o]*inv;
        g_ab[o]      = A;
        g_ab[64 + o] = beta[o] - mean*A;
    }
}

// -------------------------------------------------------- normalize + ReLU
__global__ void k_norm(float* __restrict__ out) {
    int i = blockIdx.x*256 + threadIdx.x;     // 4 elements per thread
    int o = (i >> 14) & 63;
    float A = g_ab[o], Bv = g_ab[64 + o];
    uint2 u = ((const uint2*)g_raw)[i];
    float2 fa = u2f2(u.x), fb = u2f2(u.y);
    float4 v;
    v.x = fmaxf(fmaf(fa.x, A, Bv), 0.f);
    v.y = fmaxf(fmaf(fa.y, A, Bv), 0.f);
    v.z = fmaxf(fmaf(fb.x, A, Bv), 0.f);
    v.w = fmaxf(fmaf(fb.y, A, Bv), 0.f);
    ((float4*)out)[i] = v;
}

extern "C" void kernel_launch(void* const* d_in, const int* in_sizes, int n_in,
                              void* d_out, int out_size) {
    const float* x     = (const float*)d_in[0];
    const float* w_off = (const float*)d_in[1];
    const float* b_off = (const float*)d_in[2];
    const float* w_dcn = (const float*)d_in[3];
    const float* b_dcn = (const float*)d_in[4];
    const float* gamma = (const float*)d_in[5];
    const float* beta  = (const float*)d_in[6];
    float* out = (float*)d_out;

    cudaFuncSetAttribute(k_main, cudaFuncAttributeMaxDynamicSharedMemorySize, SMEM_BYTES);

    k_zero_pad<<<512, 256>>>();
    k_winit<<<6, 256>>>(w_dcn);
    k_transpose<<<dim3(8, 2, B_*H_), dim3(32, 8)>>>(x);
    k_main<<<MAIN_BLOCKS, 256, SMEM_BYTES>>>(b_dcn, w_off, b_off);
    k_stats<<<64, 256>>>(gamma, beta);
    k_norm<<<NPIX*C_/4/256, 256>>>(out);
}